// round 1
// baseline (speedup 1.0000x reference)
#include <cuda_runtime.h>
#include <math.h>
#include <stddef.h>

// Triangle multiplicative update (outgoing), N=512, cz=ch=128, fp32.
//
// Pipeline:
//   k1<true>  : zn = LN(z); a = mask*sig(zn@Wlg+blg)*(zn@Wl+bl) -> g_a[c][i][k]
//               (blockIdx.y==1 -> b analogously into g_b[c][j][k])
//   k1<false> : g = sig(zn@Wg+bg) -> g_g[pix][c]   (row-major)
//   k2        : per channel c: X_c = A_c @ B_c^T -> g_x[c][i][j]
//   k3        : LN over c, @w_out + b_out, * g -> out[pix][c]

#define NSEQ 512
#define CDIM 128
#define NN   (NSEQ*NSEQ)          // 262144
#define APITCH 132                // smem pitch for k1 zn tile

// scratch (device globals: no allocation allowed)
__device__ float g_a[(size_t)CDIM * NN];   // aT[c][i][k]
__device__ float g_b[(size_t)CDIM * NN];   // bT[c][j][k]
__device__ float g_g[(size_t)NN * CDIM];   // g[pix][c]
__device__ float g_x[(size_t)CDIM * NN];   // xT[c][i][j]

__device__ __forceinline__ float sigmf(float x) {
    return 1.0f / (1.0f + __expf(-x));
}

// ---------------------------------------------------------------------------
// Kernel 1: fused LayerNorm + projection GEMM(s).
// Block: 256 threads, 128 rows (pixels) x 128 cols, K = 128.
// GATED: two weight sets (gate + value), epilogue mask*sigmoid(P)*Q, output
//        transposed to channel-major scratch. !GATED: sigmoid only, row-major.
// ---------------------------------------------------------------------------
template <bool GATED>
__global__ void __launch_bounds__(256)
k1_proj(const float* __restrict__ z, const float* __restrict__ mask,
        const float* __restrict__ ln_s, const float* __restrict__ ln_b,
        const float* __restrict__ Wg0, const float* __restrict__ bg0,
        const float* __restrict__ Wv0, const float* __restrict__ bv0,
        const float* __restrict__ Wg1, const float* __restrict__ bg1,
        const float* __restrict__ Wv1, const float* __restrict__ bv1)
{
    extern __shared__ float sm[];
    float* As  = sm;                                // 128*132
    float* Wg  = As + 128 * APITCH;                 // 128*128 [k][n]
    float* Wv  = GATED ? (Wg + 128 * 128) : nullptr;
    float* bgs = GATED ? (Wv + 128 * 128) : (Wg + 128 * 128);
    float* bvs = bgs + 128;

    const int tid  = threadIdx.x;
    const int pix0 = blockIdx.x * 128;

    const float *Wgp, *bgp, *Wvp = nullptr, *bvp = nullptr;
    float* outT;
    if (GATED) {
        if (blockIdx.y == 0) { Wgp = Wg0; bgp = bg0; Wvp = Wv0; bvp = bv0; outT = g_a; }
        else                 { Wgp = Wg1; bgp = bg1; Wvp = Wv1; bvp = bv1; outT = g_b; }
    } else {
        Wgp = Wg0; bgp = bg0; outT = g_g;
    }

    // stage weights (float4)
    for (int u = tid; u < 4096; u += 256) {
        ((float4*)Wg)[u] = ((const float4*)Wgp)[u];
        if (GATED) ((float4*)Wv)[u] = ((const float4*)Wvp)[u];
    }
    if (tid < 128) {
        bgs[tid] = bgp[tid];
        if (GATED) bvs[tid] = bvp[tid];
    }

    // LayerNorm: one warp per row, 16 rows each
    {
        const int warp = tid >> 5, lane = tid & 31;
        float4 s4 = ((const float4*)ln_s)[lane];
        float4 b4 = ((const float4*)ln_b)[lane];
        for (int r = warp; r < 128; r += 8) {
            float4 v = ((const float4*)(z + (size_t)(pix0 + r) * CDIM))[lane];
            float s  = v.x + v.y + v.z + v.w;
            float ss = v.x*v.x + v.y*v.y + v.z*v.z + v.w*v.w;
#pragma unroll
            for (int o = 16; o > 0; o >>= 1) {
                s  += __shfl_xor_sync(0xffffffffu, s,  o);
                ss += __shfl_xor_sync(0xffffffffu, ss, o);
            }
            float mu   = s * 0.0078125f;
            float rstd = rsqrtf(ss * 0.0078125f - mu * mu + 1e-5f);
            float4 o4;
            o4.x = (v.x - mu) * rstd * s4.x + b4.x;
            o4.y = (v.y - mu) * rstd * s4.y + b4.y;
            o4.z = (v.z - mu) * rstd * s4.z + b4.z;
            o4.w = (v.w - mu) * rstd * s4.w + b4.w;
            *(float4*)(As + r * APITCH + lane * 4) = o4;
        }
    }
    __syncthreads();

    // GEMM: 8x8 register tile per thread
    const int tx = tid & 15, ty = tid >> 4;
    float accP[8][8];
    float accQ[8][8];
#pragma unroll
    for (int i = 0; i < 8; ++i)
#pragma unroll
        for (int j = 0; j < 8; ++j) { accP[i][j] = 0.f; if (GATED) accQ[i][j] = 0.f; }

#pragma unroll 2
    for (int k = 0; k < 128; ++k) {
        float a[8];
#pragma unroll
        for (int q = 0; q < 8; ++q)
            a[q] = As[(ty * 4 + (q >> 2) * 64 + (q & 3)) * APITCH + k];
        float bg[8], bv[8];
        *(float4*)(bg + 0) = *(const float4*)(Wg + k * 128 + tx * 4);
        *(float4*)(bg + 4) = *(const float4*)(Wg + k * 128 + 64 + tx * 4);
        if (GATED) {
            *(float4*)(bv + 0) = *(const float4*)(Wv + k * 128 + tx * 4);
            *(float4*)(bv + 4) = *(const float4*)(Wv + k * 128 + 64 + tx * 4);
        }
#pragma unroll
        for (int i = 0; i < 8; ++i)
#pragma unroll
            for (int j = 0; j < 8; ++j) {
                accP[i][j] = fmaf(a[i], bg[j], accP[i][j]);
                if (GATED) accQ[i][j] = fmaf(a[i], bv[j], accQ[i][j]);
            }
    }

    if (GATED) {
        __syncthreads();             // everyone done reading As
        float* Csm = As;             // reuse: [n][r], pitch 128
#pragma unroll
        for (int i = 0; i < 8; ++i) {
            int r = ty * 4 + (i >> 2) * 64 + (i & 3);
            float mv = mask[pix0 + r];
#pragma unroll
            for (int j = 0; j < 8; ++j) {
                int n = tx * 4 + (j >> 2) * 64 + (j & 3);
                float gate = sigmf(accP[i][j] + bgs[n]);
                Csm[n * 128 + r] = mv * gate * (accQ[i][j] + bvs[n]);
            }
        }
        __syncthreads();
        for (int u = tid; u < 4096; u += 256) {
            int c = u >> 5, q = u & 31;
            float4 v = ((const float4*)(Csm + c * 128))[q];
            ((float4*)(outT + (size_t)c * NN + pix0))[q] = v;
        }
    } else {
#pragma unroll
        for (int i = 0; i < 8; ++i) {
            int r = ty * 4 + (i >> 2) * 64 + (i & 3);
            float* base = outT + (size_t)(pix0 + r) * CDIM;
#pragma unroll
            for (int jh = 0; jh < 2; ++jh) {
                int n0 = tx * 4 + jh * 64;
                float4 o;
                o.x = sigmf(accP[i][jh * 4 + 0] + bgs[n0 + 0]);
                o.y = sigmf(accP[i][jh * 4 + 1] + bgs[n0 + 1]);
                o.z = sigmf(accP[i][jh * 4 + 2] + bgs[n0 + 2]);
                o.w = sigmf(accP[i][jh * 4 + 3] + bgs[n0 + 3]);
                *(float4*)(base + n0) = o;
            }
        }
    }
}

// ---------------------------------------------------------------------------
// Kernel 2: per-channel X_c = A_c @ B_c^T  (512x512x512), 128x128 tiles.
// ---------------------------------------------------------------------------
__global__ void __launch_bounds__(256, 2)
k2_tri()
{
    __shared__ float As[128][33];
    __shared__ float Bs[128][33];

    const int tid = threadIdx.x;
    const int i0 = blockIdx.x * 128, j0 = blockIdx.y * 128;
    const size_t cbase = (size_t)blockIdx.z * NN;
    const float* Ag = g_a + cbase + (size_t)i0 * NSEQ;
    const float* Bg = g_b + cbase + (size_t)j0 * NSEQ;

    const int tx = tid & 15, ty = tid >> 4;
    float acc[8][8];
#pragma unroll
    for (int i = 0; i < 8; ++i)
#pragma unroll
        for (int j = 0; j < 8; ++j) acc[i][j] = 0.f;

    for (int k0 = 0; k0 < NSEQ; k0 += 32) {
        __syncthreads();
#pragma unroll
        for (int u = tid; u < 4096; u += 256) {
            int row = u >> 5, kk = u & 31;
            As[row][kk] = Ag[(size_t)row * NSEQ + k0 + kk];
            Bs[row][kk] = Bg[(size_t)row * NSEQ + k0 + kk];
        }
        __syncthreads();
#pragma unroll 8
        for (int k = 0; k < 32; ++k) {
            float a[8], b[8];
#pragma unroll
            for (int q = 0; q < 8; ++q)
                a[q] = As[ty * 4 + (q >> 2) * 64 + (q & 3)][k];
#pragma unroll
            for (int q = 0; q < 8; ++q)
                b[q] = Bs[tx * 4 + (q >> 2) * 64 + (q & 3)][k];
#pragma unroll
            for (int i = 0; i < 8; ++i)
#pragma unroll
                for (int j = 0; j < 8; ++j)
                    acc[i][j] = fmaf(a[i], b[j], acc[i][j]);
        }
    }

    float* Xg = g_x + cbase + (size_t)i0 * NSEQ + j0;
#pragma unroll
    for (int i = 0; i < 8; ++i) {
        int r = ty * 4 + (i >> 2) * 64 + (i & 3);
        float4 v0 = make_float4(acc[i][0], acc[i][1], acc[i][2], acc[i][3]);
        float4 v1 = make_float4(acc[i][4], acc[i][5], acc[i][6], acc[i][7]);
        *(float4*)(Xg + (size_t)r * NSEQ + tx * 4)      = v0;
        *(float4*)(Xg + (size_t)r * NSEQ + 64 + tx * 4) = v1;
    }
}

// ---------------------------------------------------------------------------
// Kernel 3: LN over channels + @w_out + b_out, gated by g -> d_out.
// ---------------------------------------------------------------------------
__global__ void __launch_bounds__(256)
k3_out(const float* __restrict__ ln_s, const float* __restrict__ ln_b,
       const float* __restrict__ w_out, const float* __restrict__ b_out,
       float* __restrict__ out)
{
    extern __shared__ float sm[];
    float* Xs   = sm;            // [c][p], pitch 128 : 16384
    float* Ws   = Xs + 16384;    // [k][n]            : 16384
    float* so   = Ws + 16384;    // 128
    float* bo   = so + 128;      // 128
    float* bou  = bo + 128;      // 128
    float* redS = bou + 128;     // 256
    float* redQ = redS + 256;    // 256
    float* mus  = redQ + 256;    // 128
    float* rss  = mus + 128;     // 128

    const int tid  = threadIdx.x;
    const int pix0 = blockIdx.x * 128;

    for (int u = tid; u < 4096; u += 256) {
        ((float4*)Ws)[u] = ((const float4*)w_out)[u];
        int c = u >> 5, q = u & 31;
        ((float4*)(Xs + c * 128))[q] =
            ((const float4*)(g_x + (size_t)c * NN + pix0))[q];
    }
    if (tid < 128) { so[tid] = ln_s[tid]; bo[tid] = ln_b[tid]; bou[tid] = b_out[tid]; }
    __syncthreads();

    // LN over c: two threads per pixel
    const int p = tid & 127, half = tid >> 7;
    {
        float s = 0.f, ss = 0.f;
        for (int c = half * 64; c < half * 64 + 64; ++c) {
            float v = Xs[c * 128 + p];
            s += v; ss += v * v;
        }
        redS[tid] = s; redQ[tid] = ss;
    }
    __syncthreads();
    if (tid < 128) {
        float S = redS[tid] + redS[tid + 128];
        float Q = redQ[tid] + redQ[tid + 128];
        float mu = S * 0.0078125f;
        mus[tid] = mu;
        rss[tid] = rsqrtf(Q * 0.0078125f - mu * mu + 1e-5f);
    }
    __syncthreads();
    {
        float mu = mus[p], rs = rss[p];
        for (int c = half * 64; c < half * 64 + 64; ++c) {
            float v = Xs[c * 128 + p];
            Xs[c * 128 + p] = (v - mu) * rs * so[c] + bo[c];
        }
    }
    __syncthreads();

    // GEMM: out[p][n] = sum_c Xs[c][p] * Ws[c][n]
    const int tx = tid & 15, ty = tid >> 4;
    float acc[8][8];
#pragma unroll
    for (int i = 0; i < 8; ++i)
#pragma unroll
        for (int j = 0; j < 8; ++j) acc[i][j] = 0.f;

#pragma unroll 4
    for (int k = 0; k < 128; ++k) {
        float a[8], b[8];
        *(float4*)(a + 0) = *(const float4*)(Xs + k * 128 + ty * 4);
        *(float4*)(a + 4) = *(const float4*)(Xs + k * 128 + 64 + ty * 4);
        *(float4*)(b + 0) = *(const float4*)(Ws + k * 128 + tx * 4);
        *(float4*)(b + 4) = *(const float4*)(Ws + k * 128 + 64 + tx * 4);
#pragma unroll
        for (int i = 0; i < 8; ++i)
#pragma unroll
            for (int j = 0; j < 8; ++j)
                acc[i][j] = fmaf(a[i], b[j], acc[i][j]);
    }

#pragma unroll
    for (int i = 0; i < 8; ++i) {
        int r = ty * 4 + (i >> 2) * 64 + (i & 3);
        size_t base = (size_t)(pix0 + r) * CDIM;
#pragma unroll
        for (int jh = 0; jh < 2; ++jh) {
            int n0 = tx * 4 + jh * 64;
            float4 gg = *(const float4*)(g_g + base + n0);
            float4 o;
            o.x = (acc[i][jh * 4 + 0] + bou[n0 + 0]) * gg.x;
            o.y = (acc[i][jh * 4 + 1] + bou[n0 + 1]) * gg.y;
            o.z = (acc[i][jh * 4 + 2] + bou[n0 + 2]) * gg.z;
            o.w = (acc[i][jh * 4 + 3] + bou[n0 + 3]) * gg.w;
            *(float4*)(out + base + n0) = o;
        }
    }
}

// ---------------------------------------------------------------------------
extern "C" void kernel_launch(void* const* d_in, const int* in_sizes, int n_in,
                              void* d_out, int out_size)
{
    const float* z        = (const float*)d_in[0];
    const float* mask     = (const float*)d_in[1];
    const float* ln_in_s  = (const float*)d_in[2];
    const float* ln_in_b  = (const float*)d_in[3];
    const float* w_left   = (const float*)d_in[4];
    const float* b_left   = (const float*)d_in[5];
    const float* w_right  = (const float*)d_in[6];
    const float* b_right  = (const float*)d_in[7];
    const float* w_lgate  = (const float*)d_in[8];
    const float* b_lgate  = (const float*)d_in[9];
    const float* w_rgate  = (const float*)d_in[10];
    const float* b_rgate  = (const float*)d_in[11];
    const float* ln_out_s = (const float*)d_in[12];
    const float* ln_out_b = (const float*)d_in[13];
    const float* w_out    = (const float*)d_in[14];
    const float* b_out    = (const float*)d_in[15];
    const float* w_gate   = (const float*)d_in[16];
    const float* b_gate   = (const float*)d_in[17];
    float* out = (float*)d_out;

    const int smem1g = (128 * APITCH + 2 * 128 * 128 + 256) * 4;   // 199680
    const int smem1p = (128 * APITCH + 128 * 128 + 128) * 4;       // 133632
    const int smem3  = (2 * 16384 + 3 * 128 + 2 * 256 + 2 * 128) * 4; // ~135680

    cudaFuncSetAttribute(k1_proj<true>,  cudaFuncAttributeMaxDynamicSharedMemorySize, smem1g);
    cudaFuncSetAttribute(k1_proj<false>, cudaFuncAttributeMaxDynamicSharedMemorySize, smem1p);
    cudaFuncSetAttribute(k3_out,         cudaFuncAttributeMaxDynamicSharedMemorySize, smem3);

    // 1) a, b projections (gated)
    k1_proj<true><<<dim3(NN / 128, 2), 256, smem1g>>>(
        z, mask, ln_in_s, ln_in_b,
        w_lgate, b_lgate, w_left, b_left,
        w_rgate, b_rgate, w_right, b_right);

    // 2) output gate g
    k1_proj<false><<<dim3(NN / 128, 1), 256, smem1p>>>(
        z, mask, ln_in_s, ln_in_b,
        w_gate, b_gate, nullptr, nullptr,
        nullptr, nullptr, nullptr, nullptr);

    // 3) triangular einsum per channel
    k2_tri<<<dim3(NSEQ / 128, NSEQ / 128, CDIM), 256>>>();

    // 4) LN + out projection + gating
    k3_out<<<dim3(NN / 128, 1), 256, smem3>>>(ln_out_s, ln_out_b, w_out, b_out, out);
}

// round 3
// speedup vs baseline: 1.2794x; 1.2794x over previous
#include <cuda_runtime.h>
#include <cuda_bf16.h>
#include <math.h>
#include <stddef.h>
#include <stdint.h>

// Triangle multiplicative update (outgoing), N=512, cz=ch=128, fp32 in/out.
//
//   k1<true>  : zn = LN(z); a = mask*sig(zn@Wlg+blg)*(zn@Wl+bl)
//               -> bf16 hi/lo channel-major scratch (g_a_hi/lo, g_b_hi/lo)
//   k1<false> : g = sig(zn@Wg+bg) -> g_g[pix][c] (fp32, row-major)
//   k2_mma    : per channel c: X_c = A_c @ B_c^T via mma.sync bf16 split
//               (3 passes: hi*hi + hi*lo + lo*hi, fp32 accum)
//   k3        : LN over c, @w_out + b_out, * g -> out

#define NSEQ 512
#define CDIM 128
#define NN   (NSEQ*NSEQ)          // 262144
#define APITCH 132

__device__ __nv_bfloat16 g_a_hi[(size_t)CDIM * NN];
__device__ __nv_bfloat16 g_a_lo[(size_t)CDIM * NN];
__device__ __nv_bfloat16 g_b_hi[(size_t)CDIM * NN];
__device__ __nv_bfloat16 g_b_lo[(size_t)CDIM * NN];
__device__ float g_g[(size_t)NN * CDIM];   // g[pix][c]
__device__ float g_x[(size_t)CDIM * NN];   // xT[c][i][j]

__device__ __forceinline__ float sigmf(float x) {
    return 1.0f / (1.0f + __expf(-x));
}
__device__ __forceinline__ unsigned pk_bf16x2(float a, float b) {
    __nv_bfloat162 t = __floats2bfloat162_rn(a, b);
    return *reinterpret_cast<unsigned*>(&t);
}
__device__ __forceinline__ uint32_t smem_u32(const void* p) {
    uint32_t a;
    asm("{ .reg .u64 t; cvta.to.shared.u64 t, %1; cvt.u32.u64 %0, t; }"
        : "=r"(a) : "l"(p));
    return a;
}
__device__ __forceinline__ void cp16(uint32_t dst, const void* src) {
    asm volatile("cp.async.cg.shared.global [%0], [%1], 16;"
                 :: "r"(dst), "l"(src) : "memory");
}
#define SWZ(o) ((o) ^ (((o) >> 3) & 0x70))

__device__ __forceinline__ void ldsm4(uint32_t addr, uint32_t* r) {
    asm volatile("ldmatrix.sync.aligned.m8n8.x4.shared.b16 {%0,%1,%2,%3}, [%4];"
                 : "=r"(r[0]), "=r"(r[1]), "=r"(r[2]), "=r"(r[3]) : "r"(addr));
}
__device__ __forceinline__ void mma_bf16(float* c, const uint32_t* a,
                                         const uint32_t* b) {
    asm volatile(
        "mma.sync.aligned.m16n8k16.row.col.f32.bf16.bf16.f32 "
        "{%0,%1,%2,%3}, {%4,%5,%6,%7}, {%8,%9}, {%0,%1,%2,%3};"
        : "+f"(c[0]), "+f"(c[1]), "+f"(c[2]), "+f"(c[3])
        : "r"(a[0]), "r"(a[1]), "r"(a[2]), "r"(a[3]), "r"(b[0]), "r"(b[1]));
}

// ---------------------------------------------------------------------------
// Kernel 1: fused LayerNorm + projection GEMM(s).
// ---------------------------------------------------------------------------
template <bool GATED>
__global__ void __launch_bounds__(256)
k1_proj(const float* __restrict__ z, const float* __restrict__ mask,
        const float* __restrict__ ln_s, const float* __restrict__ ln_b,
        const float* __restrict__ Wg0, const float* __restrict__ bg0,
        const float* __restrict__ Wv0, const float* __restrict__ bv0,
        const float* __restrict__ Wg1, const float* __restrict__ bg1,
        const float* __restrict__ Wv1, const float* __restrict__ bv1)
{
    extern __shared__ float sm[];
    float* As  = sm;                                // 128*132
    float* Wg  = As + 128 * APITCH;                 // 128*128 [k][n]
    float* Wv  = GATED ? (Wg + 128 * 128) : nullptr;
    float* bgs = GATED ? (Wv + 128 * 128) : (Wg + 128 * 128);
    float* bvs = bgs + 128;

    const int tid  = threadIdx.x;
    const int pix0 = blockIdx.x * 128;

    const float *Wgp, *bgp, *Wvp = nullptr, *bvp = nullptr;
    if (GATED) {
        if (blockIdx.y == 0) { Wgp = Wg0; bgp = bg0; Wvp = Wv0; bvp = bv0; }
        else                 { Wgp = Wg1; bgp = bg1; Wvp = Wv1; bvp = bv1; }
    } else {
        Wgp = Wg0; bgp = bg0;
    }

    for (int u = tid; u < 4096; u += 256) {
        ((float4*)Wg)[u] = ((const float4*)Wgp)[u];
        if (GATED) ((float4*)Wv)[u] = ((const float4*)Wvp)[u];
    }
    if (tid < 128) {
        bgs[tid] = bgp[tid];
        if (GATED) bvs[tid] = bvp[tid];
    }

    // LayerNorm
    {
        const int warp = tid >> 5, lane = tid & 31;
        float4 s4 = ((const float4*)ln_s)[lane];
        float4 b4 = ((const float4*)ln_b)[lane];
        for (int r = warp; r < 128; r += 8) {
            float4 v = ((const float4*)(z + (size_t)(pix0 + r) * CDIM))[lane];
            float s  = v.x + v.y + v.z + v.w;
            float ss = v.x*v.x + v.y*v.y + v.z*v.z + v.w*v.w;
#pragma unroll
            for (int o = 16; o > 0; o >>= 1) {
                s  += __shfl_xor_sync(0xffffffffu, s,  o);
                ss += __shfl_xor_sync(0xffffffffu, ss, o);
            }
            float mu   = s * 0.0078125f;
            float rstd = rsqrtf(ss * 0.0078125f - mu * mu + 1e-5f);
            float4 o4;
            o4.x = (v.x - mu) * rstd * s4.x + b4.x;
            o4.y = (v.y - mu) * rstd * s4.y + b4.y;
            o4.z = (v.z - mu) * rstd * s4.z + b4.z;
            o4.w = (v.w - mu) * rstd * s4.w + b4.w;
            *(float4*)(As + r * APITCH + lane * 4) = o4;
        }
    }
    __syncthreads();

    const int tx = tid & 15, ty = tid >> 4;
    float accP[8][8];
    float accQ[8][8];
#pragma unroll
    for (int i = 0; i < 8; ++i)
#pragma unroll
        for (int j = 0; j < 8; ++j) { accP[i][j] = 0.f; if (GATED) accQ[i][j] = 0.f; }

#pragma unroll 2
    for (int k = 0; k < 128; ++k) {
        float a[8];
#pragma unroll
        for (int q = 0; q < 8; ++q)
            a[q] = As[(ty * 4 + (q >> 2) * 64 + (q & 3)) * APITCH + k];
        float bg[8], bv[8];
        *(float4*)(bg + 0) = *(const float4*)(Wg + k * 128 + tx * 4);
        *(float4*)(bg + 4) = *(const float4*)(Wg + k * 128 + 64 + tx * 4);
        if (GATED) {
            *(float4*)(bv + 0) = *(const float4*)(Wv + k * 128 + tx * 4);
            *(float4*)(bv + 4) = *(const float4*)(Wv + k * 128 + 64 + tx * 4);
        }
#pragma unroll
        for (int i = 0; i < 8; ++i)
#pragma unroll
            for (int j = 0; j < 8; ++j) {
                accP[i][j] = fmaf(a[i], bg[j], accP[i][j]);
                if (GATED) accQ[i][j] = fmaf(a[i], bv[j], accQ[i][j]);
            }
    }

    if (GATED) {
        __syncthreads();
        float* Csm = As;             // reuse: [n][r], pitch 128
#pragma unroll
        for (int i = 0; i < 8; ++i) {
            int r = ty * 4 + (i >> 2) * 64 + (i & 3);
            float mv = mask[pix0 + r];
#pragma unroll
            for (int j = 0; j < 8; ++j) {
                int n = tx * 4 + (j >> 2) * 64 + (j & 3);
                float gate = sigmf(accP[i][j] + bgs[n]);
                Csm[n * 128 + r] = mv * gate * (accQ[i][j] + bvs[n]);
            }
        }
        __syncthreads();
        __nv_bfloat16* oh = (blockIdx.y == 0) ? g_a_hi : g_b_hi;
        __nv_bfloat16* ol = (blockIdx.y == 0) ? g_a_lo : g_b_lo;
        for (int u = tid; u < 4096; u += 256) {
            int c = u >> 5, q = u & 31;
            float4 v = ((const float4*)(Csm + c * 128))[q];
            float h0 = __bfloat162float(__float2bfloat16(v.x));
            float h1 = __bfloat162float(__float2bfloat16(v.y));
            float h2 = __bfloat162float(__float2bfloat16(v.z));
            float h3 = __bfloat162float(__float2bfloat16(v.w));
            uint2 hv, lv;
            hv.x = pk_bf16x2(v.x, v.y);
            hv.y = pk_bf16x2(v.z, v.w);
            lv.x = pk_bf16x2(v.x - h0, v.y - h1);
            lv.y = pk_bf16x2(v.z - h2, v.w - h3);
            *((uint2*)(oh + (size_t)c * NN + pix0) + q) = hv;
            *((uint2*)(ol + (size_t)c * NN + pix0) + q) = lv;
        }
    } else {
#pragma unroll
        for (int i = 0; i < 8; ++i) {
            int r = ty * 4 + (i >> 2) * 64 + (i & 3);
            float* base = g_g + (size_t)(pix0 + r) * CDIM;
#pragma unroll
            for (int jh = 0; jh < 2; ++jh) {
                int n0 = tx * 4 + jh * 64;
                float4 o;
                o.x = sigmf(accP[i][jh * 4 + 0] + bgs[n0 + 0]);
                o.y = sigmf(accP[i][jh * 4 + 1] + bgs[n0 + 1]);
                o.z = sigmf(accP[i][jh * 4 + 2] + bgs[n0 + 2]);
                o.w = sigmf(accP[i][jh * 4 + 3] + bgs[n0 + 3]);
                *(float4*)(base + n0) = o;
            }
        }
    }
}

// ---------------------------------------------------------------------------
// Kernel 2: per-channel X_c = A_c @ B_c^T via mma.sync bf16 hi/lo split.
// CTA tile 128x128, 8 warps (2x4), warp tile 64x32, K-chunks of 64, 2 stages.
// SMEM stage: [Ah 16K][Al 16K][Bh 16K][Bl 16K] = 64KB, SW128-swizzled rows.
// ---------------------------------------------------------------------------
#define K2S 65536u

__global__ void __launch_bounds__(256, 1)
k2_mma()
{
    extern __shared__ char sm2[];
    const uint32_t smb = smem_u32(sm2);
    const int tid  = threadIdx.x;
    const int lane = tid & 31, wid = tid >> 5;
    const int wm = wid & 1, wn = wid >> 1;          // 2 x 4 warp grid
    const int i0 = blockIdx.x * 128, j0 = blockIdx.y * 128;
    const size_t cbase = (size_t)blockIdx.z * NN;

    const __nv_bfloat16* Ah = g_a_hi + cbase + (size_t)i0 * NSEQ;
    const __nv_bfloat16* Al = g_a_lo + cbase + (size_t)i0 * NSEQ;
    const __nv_bfloat16* Bh = g_b_hi + cbase + (size_t)j0 * NSEQ;
    const __nv_bfloat16* Bl = g_b_lo + cbase + (size_t)j0 * NSEQ;

    float acc[4][4][4];
#pragma unroll
    for (int mt = 0; mt < 4; ++mt)
#pragma unroll
        for (int nt = 0; nt < 4; ++nt)
#pragma unroll
            for (int q = 0; q < 4; ++q) acc[mt][nt][q] = 0.f;

    // precomputed ldmatrix swizzled offsets (within a 16KB part)
    const int arow = wm * 64 + (lane & 15);
    const int bnr  = wn * 32 + (lane & 7) + ((lane >> 4) << 3);
    const uint32_t a_koff = (uint32_t)((lane >> 4) << 4);        // bytes
    const uint32_t b_koff = (uint32_t)(((lane >> 3) & 1) << 4);  // bytes

    // stage loader: 4096 x 16B total, 16 per thread
#define K2_LOAD(kc, stg)                                                      \
    do {                                                                      \
        const int ke = (kc) * 64;                                             \
        _Pragma("unroll")                                                     \
        for (int t = 0; t < 4; ++t) {                                         \
            int v = tid + t * 256; int r = v >> 3, cu = v & 7;                \
            uint32_t so = SWZ((uint32_t)(r * 128 + cu * 16));                 \
            const size_t go = (size_t)r * NSEQ + ke + cu * 8;                 \
            cp16((stg) + so,           Ah + go);                              \
            cp16((stg) + 16384u + so,  Al + go);                              \
            cp16((stg) + 32768u + so,  Bh + go);                              \
            cp16((stg) + 49152u + so,  Bl + go);                              \
        }                                                                     \
        asm volatile("cp.async.commit_group;" ::: "memory");                  \
    } while (0)

    K2_LOAD(0, smb);

    for (int kc = 0; kc < 8; ++kc) {
        const uint32_t stg = smb + (uint32_t)(kc & 1) * K2S;
        if (kc < 7) K2_LOAD(kc + 1, smb + (uint32_t)((kc + 1) & 1) * K2S);
        if (kc < 7) asm volatile("cp.async.wait_group 1;" ::: "memory");
        else        asm volatile("cp.async.wait_group 0;" ::: "memory");
        __syncthreads();

#pragma unroll
        for (int k16 = 0; k16 < 4; ++k16) {
            const uint32_t kbA = (uint32_t)(k16 * 32) + a_koff;
            const uint32_t kbB = (uint32_t)(k16 * 32) + b_koff;
            // B fragments: 2 x ldmatrix.x4 per precision -> 4 n8 tiles
            uint32_t bh[4][2], bl[4][2];
#pragma unroll
            for (int ng = 0; ng < 2; ++ng) {
                uint32_t r4[4];
                uint32_t off = SWZ((uint32_t)((bnr + ng * 16) * 128) + kbB);
                ldsm4(stg + 32768u + off, r4);
                bh[ng * 2 + 0][0] = r4[0]; bh[ng * 2 + 0][1] = r4[1];
                bh[ng * 2 + 1][0] = r4[2]; bh[ng * 2 + 1][1] = r4[3];
                ldsm4(stg + 49152u + off, r4);
                bl[ng * 2 + 0][0] = r4[0]; bl[ng * 2 + 0][1] = r4[1];
                bl[ng * 2 + 1][0] = r4[2]; bl[ng * 2 + 1][1] = r4[3];
            }
#pragma unroll
            for (int mt = 0; mt < 4; ++mt) {
                uint32_t ah[4], al[4];
                uint32_t off = SWZ((uint32_t)((arow + mt * 16) * 128) + kbA);
                ldsm4(stg + off, ah);
                ldsm4(stg + 16384u + off, al);
#pragma unroll
                for (int nt = 0; nt < 4; ++nt) {
                    mma_bf16(acc[mt][nt], ah, bh[nt]);
                    mma_bf16(acc[mt][nt], ah, bl[nt]);
                    mma_bf16(acc[mt][nt], al, bh[nt]);
                }
            }
        }
        __syncthreads();
    }

    // epilogue: direct float2 stores
    float* Xg = g_x + cbase + (size_t)(i0 + wm * 64) * NSEQ + j0 + wn * 32;
    const int rr = lane >> 2, cc = (lane & 3) * 2;
#pragma unroll
    for (int mt = 0; mt < 4; ++mt)
#pragma unroll
        for (int nt = 0; nt < 4; ++nt) {
            float* p0 = Xg + (size_t)(mt * 16 + rr) * NSEQ + nt * 8 + cc;
            *(float2*)p0            = make_float2(acc[mt][nt][0], acc[mt][nt][1]);
            *(float2*)(p0 + 8 * NSEQ) = make_float2(acc[mt][nt][2], acc[mt][nt][3]);
        }
#undef K2_LOAD
}

// ---------------------------------------------------------------------------
// Kernel 3: LN over channels + @w_out + b_out, gated by g -> d_out.
// ---------------------------------------------------------------------------
__global__ void __launch_bounds__(256)
k3_out(const float* __restrict__ ln_s, const float* __restrict__ ln_b,
       const float* __restrict__ w_out, const float* __restrict__ b_out,
       float* __restrict__ out)
{
    extern __shared__ float sm[];
    float* Xs   = sm;            // [c][p], pitch 128 : 16384
    float* Ws   = Xs + 16384;    // [k][n]            : 16384
    float* so   = Ws + 16384;
    float* bo   = so + 128;
    float* bou  = bo + 128;
    float* redS = bou + 128;     // 256
    float* redQ = redS + 256;    // 256
    float* mus  = redQ + 256;    // 128
    float* rss  = mus + 128;     // 128

    const int tid  = threadIdx.x;
    const int pix0 = blockIdx.x * 128;

    for (int u = tid; u < 4096; u += 256) {
        ((float4*)Ws)[u] = ((const float4*)w_out)[u];
        int c = u >> 5, q = u & 31;
        ((float4*)(Xs + c * 128))[q] =
            ((const float4*)(g_x + (size_t)c * NN + pix0))[q];
    }
    if (tid < 128) { so[tid] = ln_s[tid]; bo[tid] = ln_b[tid]; bou[tid] = b_out[tid]; }
    __syncthreads();

    const int p = tid & 127, half = tid >> 7;
    {
        float s = 0.f, ss = 0.f;
        for (int c = half * 64; c < half * 64 + 64; ++c) {
            float v = Xs[c * 128 + p];
            s += v; ss += v * v;
        }
        redS[tid] = s; redQ[tid] = ss;
    }
    __syncthreads();
    if (tid < 128) {
        float S = redS[tid] + redS[tid + 128];
        float Q = redQ[tid] + redQ[tid + 128];
        float mu = S * 0.0078125f;
        mus[tid] = mu;
        rss[tid] = rsqrtf(Q * 0.0078125f - mu * mu + 1e-5f);
    }
    __syncthreads();
    {
        float mu = mus[p], rs = rss[p];
        for (int c = half * 64; c < half * 64 + 64; ++c) {
            float v = Xs[c * 128 + p];
            Xs[c * 128 + p] = (v - mu) * rs * so[c] + bo[c];
        }
    }
    __syncthreads();

    const int tx = tid & 15, ty = tid >> 4;
    float acc[8][8];
#pragma unroll
    for (int i = 0; i < 8; ++i)
#pragma unroll
        for (int j = 0; j < 8; ++j) acc[i][j] = 0.f;

#pragma unroll 4
    for (int k = 0; k < 128; ++k) {
        float a[8], b[8];
        *(float4*)(a + 0) = *(const float4*)(Xs + k * 128 + ty * 4);
        *(float4*)(a + 4) = *(const float4*)(Xs + k * 128 + 64 + ty * 4);
        *(float4*)(b + 0) = *(const float4*)(Ws + k * 128 + tx * 4);
        *(float4*)(b + 4) = *(const float4*)(Ws + k * 128 + 64 + tx * 4);
#pragma unroll
        for (int i = 0; i < 8; ++i)
#pragma unroll
            for (int j = 0; j < 8; ++j)
                acc[i][j] = fmaf(a[i], b[j], acc[i][j]);
    }

#pragma unroll
    for (int i = 0; i < 8; ++i) {
        int r = ty * 4 + (i >> 2) * 64 + (i & 3);
        size_t base = (size_t)(pix0 + r) * CDIM;
#pragma unroll
        for (int jh = 0; jh < 2; ++jh) {
            int n0 = tx * 4 + jh * 64;
            float4 gg = *(const float4*)(g_g + base + n0);
            float4 o;
            o.x = (acc[i][jh * 4 + 0] + bou[n0 + 0]) * gg.x;
            o.y = (acc[i][jh * 4 + 1] + bou[n0 + 1]) * gg.y;
            o.z = (acc[i][jh * 4 + 2] + bou[n0 + 2]) * gg.z;
            o.w = (acc[i][jh * 4 + 3] + bou[n0 + 3]) * gg.w;
            *(float4*)(out + base + n0) = o;
        }
    }
}

// ---------------------------------------------------------------------------
extern "C" void kernel_launch(void* const* d_in, const int* in_sizes, int n_in,
                              void* d_out, int out_size)
{
    const float* z        = (const float*)d_in[0];
    const float* mask     = (const float*)d_in[1];
    const float* ln_in_s  = (const float*)d_in[2];
    const float* ln_in_b  = (const float*)d_in[3];
    const float* w_left   = (const float*)d_in[4];
    const float* b_left   = (const float*)d_in[5];
    const float* w_right  = (const float*)d_in[6];
    const float* b_right  = (const float*)d_in[7];
    const float* w_lgate  = (const float*)d_in[8];
    const float* b_lgate  = (const float*)d_in[9];
    const float* w_rgate  = (const float*)d_in[10];
    const float* b_rgate  = (const float*)d_in[11];
    const float* ln_out_s = (const float*)d_in[12];
    const float* ln_out_b = (const float*)d_in[13];
    const float* w_out    = (const float*)d_in[14];
    const float* b_out    = (const float*)d_in[15];
    const float* w_gate   = (const float*)d_in[16];
    const float* b_gate   = (const float*)d_in[17];
    float* out = (float*)d_out;

    const int smem1g = (128 * APITCH + 2 * 128 * 128 + 256) * 4;
    const int smem1p = (128 * APITCH + 128 * 128 + 128) * 4;
    const int smem2  = 2 * (int)K2S;                      // 131072
    const int smem3  = (2 * 16384 + 3 * 128 + 2 * 256 + 2 * 128) * 4;

    cudaFuncSetAttribute(k1_proj<true>,  cudaFuncAttributeMaxDynamicSharedMemorySize, smem1g);
    cudaFuncSetAttribute(k1_proj<false>, cudaFuncAttributeMaxDynamicSharedMemorySize, smem1p);
    cudaFuncSetAttribute(k2_mma,         cudaFuncAttributeMaxDynamicSharedMemorySize, smem2);
    cudaFuncSetAttribute(k3_out,         cudaFuncAttributeMaxDynamicSharedMemorySize, smem3);

    k1_proj<true><<<dim3(NN / 128, 2), 256, smem1g>>>(
        z, mask, ln_in_s, ln_in_b,
        w_lgate, b_lgate, w_left, b_left,
        w_rgate, b_rgate, w_right, b_right);

    k1_proj<false><<<dim3(NN / 128, 1), 256, smem1p>>>(
        z, mask, ln_in_s, ln_in_b,
        w_gate, b_gate, nullptr, nullptr,
        nullptr, nullptr, nullptr, nullptr);

    k2_mma<<<dim3(NSEQ / 128, NSEQ / 128, CDIM), 256, smem2>>>();

    k3_out<<<dim3(NN / 128, 1), 256, smem3>>>(ln_out_s, ln_out_b, w_out, b_out, out);
}

// round 4
// speedup vs baseline: 1.8762x; 1.4665x over previous
#include <cuda_runtime.h>
#include <cuda_bf16.h>
#include <math.h>
#include <stddef.h>
#include <stdint.h>

// Triangle multiplicative update (outgoing), N=512, cz=ch=128, fp32 in/out.
// All GEMMs on tensor cores via mma.sync bf16 hi/lo split (3 passes, fp32 acc).

#define NSEQ 512
#define CDIM 128
#define NN   (NSEQ*NSEQ)          // 262144
#define PIT  136                  // bf16 smem pitch (elements)
#define PITB 272                  // bytes

__device__ __nv_bfloat16 g_a_hi[(size_t)CDIM * NN];
__device__ __nv_bfloat16 g_a_lo[(size_t)CDIM * NN];
__device__ __nv_bfloat16 g_b_hi[(size_t)CDIM * NN];
__device__ __nv_bfloat16 g_b_lo[(size_t)CDIM * NN];
__device__ float g_g[(size_t)NN * CDIM];   // g[pix][c]
__device__ float g_x[(size_t)CDIM * NN];   // xT[c][i][j]

__device__ __forceinline__ float sigmf(float x) {
    return 1.0f / (1.0f + __expf(-x));
}
__device__ __forceinline__ unsigned pk_bf16x2(float a, float b) {
    __nv_bfloat162 t = __floats2bfloat162_rn(a, b);
    return *reinterpret_cast<unsigned*>(&t);
}
__device__ __forceinline__ float bf16_res(float v) {   // v - bf16(v)
    return v - __bfloat162float(__float2bfloat16(v));
}
__device__ __forceinline__ uint32_t smem_u32(const void* p) {
    uint32_t a;
    asm("{ .reg .u64 t; cvta.to.shared.u64 t, %1; cvt.u32.u64 %0, t; }"
        : "=r"(a) : "l"(p));
    return a;
}
__device__ __forceinline__ void cp16(uint32_t dst, const void* src) {
    asm volatile("cp.async.cg.shared.global [%0], [%1], 16;"
                 :: "r"(dst), "l"(src) : "memory");
}
#define SWZ(o) ((o) ^ (((o) >> 3) & 0x70))

__device__ __forceinline__ void ldsm4(uint32_t addr, uint32_t* r) {
    asm volatile("ldmatrix.sync.aligned.m8n8.x4.shared.b16 {%0,%1,%2,%3}, [%4];"
                 : "=r"(r[0]), "=r"(r[1]), "=r"(r[2]), "=r"(r[3]) : "r"(addr));
}
__device__ __forceinline__ void ldsm4_t(uint32_t addr, uint32_t* r) {
    asm volatile("ldmatrix.sync.aligned.m8n8.x4.trans.shared.b16 {%0,%1,%2,%3}, [%4];"
                 : "=r"(r[0]), "=r"(r[1]), "=r"(r[2]), "=r"(r[3]) : "r"(addr));
}
__device__ __forceinline__ void mma_bf16(float* c, const uint32_t* a,
                                         const uint32_t* b) {
    asm volatile(
        "mma.sync.aligned.m16n8k16.row.col.f32.bf16.bf16.f32 "
        "{%0,%1,%2,%3}, {%4,%5,%6,%7}, {%8,%9}, {%0,%1,%2,%3};"
        : "+f"(c[0]), "+f"(c[1]), "+f"(c[2]), "+f"(c[3])
        : "r"(a[0]), "r"(a[1]), "r"(a[2]), "r"(a[3]), "r"(b[0]), "r"(b[1]));
}

// split a float4 into hi/lo bf16x2 pairs
__device__ __forceinline__ void split4(float4 v, uint2& hv, uint2& lv) {
    hv.x = pk_bf16x2(v.x, v.y);
    hv.y = pk_bf16x2(v.z, v.w);
    lv.x = pk_bf16x2(bf16_res(v.x), bf16_res(v.y));
    lv.y = pk_bf16x2(bf16_res(v.z), bf16_res(v.w));
}

// ---------------------------------------------------------------------------
// Kernel 1: fused LayerNorm + projection via mma.sync (split bf16).
// GATED: C[ch][p] orientation (A = W^T trans-ldsm, B = zn), epilogue writes
//        channel-major bf16 hi/lo scratch directly.
// !GATED: C[p][ch] orientation (A = zn, B = W^T trans-ldsm) -> g_g row-major.
// ---------------------------------------------------------------------------
template <bool GATED>
__global__ void __launch_bounds__(256, 1)
k1_mma(const float* __restrict__ z, const float* __restrict__ mask,
       const float* __restrict__ ln_s, const float* __restrict__ ln_b,
       const float* __restrict__ Wg0, const float* __restrict__ bg0,
       const float* __restrict__ Wv0, const float* __restrict__ bv0,
       const float* __restrict__ Wg1, const float* __restrict__ bg1,
       const float* __restrict__ Wv1, const float* __restrict__ bv1)
{
    extern __shared__ char smraw[];
    __nv_bfloat16* znh = (__nv_bfloat16*)smraw;           // [p][k] pitch 136
    __nv_bfloat16* znl = znh + 128 * PIT;
    __nv_bfloat16* Wgh = znl + 128 * PIT;                 // [k][n] pitch 136
    __nv_bfloat16* Wgl = Wgh + 128 * PIT;
    __nv_bfloat16* Wvh = Wgl + 128 * PIT;                 // gated only
    __nv_bfloat16* Wvl = Wvh + 128 * PIT;
    float* bgs = (float*)(GATED ? (void*)(Wvl + 128 * PIT)
                                : (void*)(Wgl + 128 * PIT));
    float* bvs = bgs + 128;
    float* msm = bvs + 128;

    const int tid = threadIdx.x, lane = tid & 31, wid = tid >> 5;
    const int pix0 = blockIdx.x * 128;

    const float *Wgp, *bgp, *Wvp = nullptr, *bvp = nullptr;
    if (GATED) {
        if (blockIdx.y == 0) { Wgp = Wg0; bgp = bg0; Wvp = Wv0; bvp = bv0; }
        else                 { Wgp = Wg1; bgp = bg1; Wvp = Wv1; bvp = bv1; }
    } else {
        Wgp = Wg0; bgp = bg0;
    }

    if (tid < 128) {
        bgs[tid] = bgp[tid];
        if (GATED) { bvs[tid] = bvp[tid]; msm[tid] = mask[pix0 + tid]; }
    }

    // load + hi/lo split weights into smem
    for (int u = tid; u < 4096; u += 256) {
        int k = u >> 5, n4 = (u & 31) * 4;
        float4 w = ((const float4*)Wgp)[u];
        uint2 hv, lv;
        split4(w, hv, lv);
        *(uint2*)(&Wgh[k * PIT + n4]) = hv;
        *(uint2*)(&Wgl[k * PIT + n4]) = lv;
        if (GATED) {
            float4 w2 = ((const float4*)Wvp)[u];
            split4(w2, hv, lv);
            *(uint2*)(&Wvh[k * PIT + n4]) = hv;
            *(uint2*)(&Wvl[k * PIT + n4]) = lv;
        }
    }

    // LayerNorm -> split zn into smem (one warp per row, 16 rows each)
    {
        float4 s4 = ((const float4*)ln_s)[lane];
        float4 b4 = ((const float4*)ln_b)[lane];
        for (int r = wid; r < 128; r += 8) {
            float4 v = ((const float4*)(z + (size_t)(pix0 + r) * CDIM))[lane];
            float s  = v.x + v.y + v.z + v.w;
            float ss = v.x*v.x + v.y*v.y + v.z*v.z + v.w*v.w;
#pragma unroll
            for (int o = 16; o > 0; o >>= 1) {
                s  += __shfl_xor_sync(0xffffffffu, s,  o);
                ss += __shfl_xor_sync(0xffffffffu, ss, o);
            }
            float mu   = s * 0.0078125f;
            float rstd = rsqrtf(ss * 0.0078125f - mu * mu + 1e-5f);
            float4 o4;
            o4.x = (v.x - mu) * rstd * s4.x + b4.x;
            o4.y = (v.y - mu) * rstd * s4.y + b4.y;
            o4.z = (v.z - mu) * rstd * s4.z + b4.z;
            o4.w = (v.w - mu) * rstd * s4.w + b4.w;
            uint2 hv, lv;
            split4(o4, hv, lv);
            *(uint2*)(&znh[r * PIT + lane * 4]) = hv;
            *(uint2*)(&znl[r * PIT + lane * 4]) = lv;
        }
    }
    __syncthreads();

    const int wm = wid & 1, wn = wid >> 1;   // 2 (M) x 4 (N) warp grid
    const uint32_t zh = smem_u32(znh), zl = smem_u32(znl);
    const uint32_t wgh = smem_u32(Wgh), wgl = smem_u32(Wgl);
    const uint32_t wvh = GATED ? smem_u32(Wvh) : 0;
    const uint32_t wvl = GATED ? smem_u32(Wvl) : 0;

    float P[4][4][4], Q[4][4][4];
#pragma unroll
    for (int a = 0; a < 4; ++a)
#pragma unroll
        for (int b = 0; b < 4; ++b)
#pragma unroll
            for (int q = 0; q < 4; ++q) { P[a][b][q] = 0.f; if (GATED) Q[a][b][q] = 0.f; }

    if (GATED) {
        // A = W^T (trans): row k, col ch ; B = zn (non-trans): row p
        const int at_row = (lane & 7) + ((lane >> 4) << 3);
        const int at_col = ((lane >> 3) & 1) << 3;
        const int bp_row = wn * 32 + (lane & 7) + ((lane >> 4) << 3);
        const uint32_t bko = ((lane >> 3) & 1) * 16;

#pragma unroll
        for (int k16 = 0; k16 < 8; ++k16) {
            const int kb = k16 * 16;
            uint32_t bh[4][2], bl[4][2];
#pragma unroll
            for (int ng = 0; ng < 2; ++ng) {
                uint32_t r4[4];
                uint32_t boff = (uint32_t)((bp_row + ng * 16) * PITB) + kb * 2 + bko;
                ldsm4(zh + boff, r4);
                bh[ng*2][0] = r4[0]; bh[ng*2][1] = r4[1];
                bh[ng*2+1][0] = r4[2]; bh[ng*2+1][1] = r4[3];
                ldsm4(zl + boff, r4);
                bl[ng*2][0] = r4[0]; bl[ng*2][1] = r4[1];
                bl[ng*2+1][0] = r4[2]; bl[ng*2+1][1] = r4[3];
            }
            uint32_t aoff[4];
#pragma unroll
            for (int mt = 0; mt < 4; ++mt)
                aoff[mt] = (uint32_t)((kb + at_row) * PITB) +
                           (wm * 64 + mt * 16 + at_col) * 2;
            uint32_t a[4][4];
#pragma unroll
            for (int mt = 0; mt < 4; ++mt) ldsm4_t(wgh + aoff[mt], a[mt]);
#pragma unroll
            for (int mt = 0; mt < 4; ++mt)
#pragma unroll
                for (int nt = 0; nt < 4; ++nt) {
                    mma_bf16(P[mt][nt], a[mt], bh[nt]);
                    mma_bf16(P[mt][nt], a[mt], bl[nt]);
                }
#pragma unroll
            for (int mt = 0; mt < 4; ++mt) ldsm4_t(wgl + aoff[mt], a[mt]);
#pragma unroll
            for (int mt = 0; mt < 4; ++mt)
#pragma unroll
                for (int nt = 0; nt < 4; ++nt)
                    mma_bf16(P[mt][nt], a[mt], bh[nt]);
#pragma unroll
            for (int mt = 0; mt < 4; ++mt) ldsm4_t(wvh + aoff[mt], a[mt]);
#pragma unroll
            for (int mt = 0; mt < 4; ++mt)
#pragma unroll
                for (int nt = 0; nt < 4; ++nt) {
                    mma_bf16(Q[mt][nt], a[mt], bh[nt]);
                    mma_bf16(Q[mt][nt], a[mt], bl[nt]);
                }
#pragma unroll
            for (int mt = 0; mt < 4; ++mt) ldsm4_t(wvl + aoff[mt], a[mt]);
#pragma unroll
            for (int mt = 0; mt < 4; ++mt)
#pragma unroll
                for (int nt = 0; nt < 4; ++nt)
                    mma_bf16(Q[mt][nt], a[mt], bh[nt]);
        }

        // epilogue: mask * sig(P + bg) * (Q + bv) -> channel-major hi/lo
        __nv_bfloat16* oh = (blockIdx.y == 0) ? g_a_hi : g_b_hi;
        __nv_bfloat16* ol = (blockIdx.y == 0) ? g_a_lo : g_b_lo;
#pragma unroll
        for (int mt = 0; mt < 4; ++mt) {
            int ch = wm * 64 + mt * 16 + (lane >> 2);
            float bg0 = bgs[ch], bg1 = bgs[ch + 8];
            float bv0 = bvs[ch], bv1 = bvs[ch + 8];
            size_t r0 = (size_t)ch * NN + pix0;
            size_t r1 = (size_t)(ch + 8) * NN + pix0;
#pragma unroll
            for (int nt = 0; nt < 4; ++nt) {
                int p = wn * 32 + nt * 8 + (lane & 3) * 2;
                float m0 = msm[p], m1 = msm[p + 1];
                float v00 = m0 * sigmf(P[mt][nt][0] + bg0) * (Q[mt][nt][0] + bv0);
                float v01 = m1 * sigmf(P[mt][nt][1] + bg0) * (Q[mt][nt][1] + bv0);
                float v10 = m0 * sigmf(P[mt][nt][2] + bg1) * (Q[mt][nt][2] + bv1);
                float v11 = m1 * sigmf(P[mt][nt][3] + bg1) * (Q[mt][nt][3] + bv1);
                *(uint32_t*)(oh + r0 + p) = pk_bf16x2(v00, v01);
                *(uint32_t*)(ol + r0 + p) = pk_bf16x2(bf16_res(v00), bf16_res(v01));
                *(uint32_t*)(oh + r1 + p) = pk_bf16x2(v10, v11);
                *(uint32_t*)(ol + r1 + p) = pk_bf16x2(bf16_res(v10), bf16_res(v11));
            }
        }
    } else {
        // A = zn (non-trans): row p ; B = W^T (trans): row k, col ch
        const int a_row = wm * 64 + (lane & 15);
        const uint32_t ako = (lane >> 4) * 16;
        const int bt_row = (lane & 7) + (((lane >> 3) & 1) << 3);
        const int bt_col = (lane >> 4) << 3;

#pragma unroll
        for (int k16 = 0; k16 < 8; ++k16) {
            const int kb = k16 * 16;
            uint32_t bh[4][2], bl[4][2];
#pragma unroll
            for (int ng = 0; ng < 2; ++ng) {
                uint32_t r4[4];
                uint32_t boff = (uint32_t)((kb + bt_row) * PITB) +
                                (wn * 32 + ng * 16 + bt_col) * 2;
                ldsm4_t(wgh + boff, r4);
                bh[ng*2][0] = r4[0]; bh[ng*2][1] = r4[1];
                bh[ng*2+1][0] = r4[2]; bh[ng*2+1][1] = r4[3];
                ldsm4_t(wgl + boff, r4);
                bl[ng*2][0] = r4[0]; bl[ng*2][1] = r4[1];
                bl[ng*2+1][0] = r4[2]; bl[ng*2+1][1] = r4[3];
            }
            uint32_t ah[4][4], al[4][4];
#pragma unroll
            for (int mt = 0; mt < 4; ++mt) {
                uint32_t aoff = (uint32_t)((a_row + mt * 16) * PITB) + kb * 2 + ako;
                ldsm4(zh + aoff, ah[mt]);
                ldsm4(zl + aoff, al[mt]);
            }
#pragma unroll
            for (int mt = 0; mt < 4; ++mt)
#pragma unroll
                for (int nt = 0; nt < 4; ++nt) {
                    mma_bf16(P[mt][nt], ah[mt], bh[nt]);
                    mma_bf16(P[mt][nt], ah[mt], bl[nt]);
                    mma_bf16(P[mt][nt], al[mt], bh[nt]);
                }
        }

        // epilogue: sigmoid -> g_g[p][ch]
#pragma unroll
        for (int mt = 0; mt < 4; ++mt) {
            int p0 = pix0 + wm * 64 + mt * 16 + (lane >> 2);
#pragma unroll
            for (int nt = 0; nt < 4; ++nt) {
                int ch = wn * 32 + nt * 8 + (lane & 3) * 2;
                float b0 = bgs[ch], b1 = bgs[ch + 1];
                float2 v0 = make_float2(sigmf(P[mt][nt][0] + b0),
                                        sigmf(P[mt][nt][1] + b1));
                float2 v1 = make_float2(sigmf(P[mt][nt][2] + b0),
                                        sigmf(P[mt][nt][3] + b1));
                *(float2*)(g_g + (size_t)p0 * CDIM + ch) = v0;
                *(float2*)(g_g + (size_t)(p0 + 8) * CDIM + ch) = v1;
            }
        }
    }
}

// ---------------------------------------------------------------------------
// Kernel 2: per-channel X_c = A_c @ B_c^T via mma.sync bf16 hi/lo split.
// (unchanged from round 3)
// ---------------------------------------------------------------------------
#define K2S 65536u

__global__ void __launch_bounds__(256, 1)
k2_mma()
{
    extern __shared__ char sm2[];
    const uint32_t smb = smem_u32(sm2);
    const int tid  = threadIdx.x;
    const int lane = tid & 31, wid = tid >> 5;
    const int wm = wid & 1, wn = wid >> 1;
    const int i0 = blockIdx.x * 128, j0 = blockIdx.y * 128;
    const size_t cbase = (size_t)blockIdx.z * NN;

    const __nv_bfloat16* Ah = g_a_hi + cbase + (size_t)i0 * NSEQ;
    const __nv_bfloat16* Al = g_a_lo + cbase + (size_t)i0 * NSEQ;
    const __nv_bfloat16* Bh = g_b_hi + cbase + (size_t)j0 * NSEQ;
    const __nv_bfloat16* Bl = g_b_lo + cbase + (size_t)j0 * NSEQ;

    float acc[4][4][4];
#pragma unroll
    for (int mt = 0; mt < 4; ++mt)
#pragma unroll
        for (int nt = 0; nt < 4; ++nt)
#pragma unroll
            for (int q = 0; q < 4; ++q) acc[mt][nt][q] = 0.f;

    const int arow = wm * 64 + (lane & 15);
    const int bnr  = wn * 32 + (lane & 7) + ((lane >> 4) << 3);
    const uint32_t a_koff = (uint32_t)((lane >> 4) << 4);
    const uint32_t b_koff = (uint32_t)(((lane >> 3) & 1) << 4);

#define K2_LOAD(kc, stg)                                                      \
    do {                                                                      \
        const int ke = (kc) * 64;                                             \
        _Pragma("unroll")                                                     \
        for (int t = 0; t < 4; ++t) {                                         \
            int v = tid + t * 256; int r = v >> 3, cu = v & 7;                \
            uint32_t so = SWZ((uint32_t)(r * 128 + cu * 16));                 \
            const size_t go = (size_t)r * NSEQ + ke + cu * 8;                 \
            cp16((stg) + so,           Ah + go);                              \
            cp16((stg) + 16384u + so,  Al + go);                              \
            cp16((stg) + 32768u + so,  Bh + go);                              \
            cp16((stg) + 49152u + so,  Bl + go);                              \
        }                                                                     \
        asm volatile("cp.async.commit_group;" ::: "memory");                  \
    } while (0)

    K2_LOAD(0, smb);

    for (int kc = 0; kc < 8; ++kc) {
        const uint32_t stg = smb + (uint32_t)(kc & 1) * K2S;
        if (kc < 7) K2_LOAD(kc + 1, smb + (uint32_t)((kc + 1) & 1) * K2S);
        if (kc < 7) asm volatile("cp.async.wait_group 1;" ::: "memory");
        else        asm volatile("cp.async.wait_group 0;" ::: "memory");
        __syncthreads();

#pragma unroll
        for (int k16 = 0; k16 < 4; ++k16) {
            const uint32_t kbA = (uint32_t)(k16 * 32) + a_koff;
            const uint32_t kbB = (uint32_t)(k16 * 32) + b_koff;
            uint32_t bh[4][2], bl[4][2];
#pragma unroll
            for (int ng = 0; ng < 2; ++ng) {
                uint32_t r4[4];
                uint32_t off = SWZ((uint32_t)((bnr + ng * 16) * 128) + kbB);
                ldsm4(stg + 32768u + off, r4);
                bh[ng * 2 + 0][0] = r4[0]; bh[ng * 2 + 0][1] = r4[1];
                bh[ng * 2 + 1][0] = r4[2]; bh[ng * 2 + 1][1] = r4[3];
                ldsm4(stg + 49152u + off, r4);
                bl[ng * 2 + 0][0] = r4[0]; bl[ng * 2 + 0][1] = r4[1];
                bl[ng * 2 + 1][0] = r4[2]; bl[ng * 2 + 1][1] = r4[3];
            }
#pragma unroll
            for (int mt = 0; mt < 4; ++mt) {
                uint32_t ah[4], al[4];
                uint32_t off = SWZ((uint32_t)((arow + mt * 16) * 128) + kbA);
                ldsm4(stg + off, ah);
                ldsm4(stg + 16384u + off, al);
#pragma unroll
                for (int nt = 0; nt < 4; ++nt) {
                    mma_bf16(acc[mt][nt], ah, bh[nt]);
                    mma_bf16(acc[mt][nt], ah, bl[nt]);
                    mma_bf16(acc[mt][nt], al, bh[nt]);
                }
            }
        }
        __syncthreads();
    }

    float* Xg = g_x + cbase + (size_t)(i0 + wm * 64) * NSEQ + j0 + wn * 32;
    const int rr = lane >> 2, cc = (lane & 3) * 2;
#pragma unroll
    for (int mt = 0; mt < 4; ++mt)
#pragma unroll
        for (int nt = 0; nt < 4; ++nt) {
            float* p0 = Xg + (size_t)(mt * 16 + rr) * NSEQ + nt * 8 + cc;
            *(float2*)p0              = make_float2(acc[mt][nt][0], acc[mt][nt][1]);
            *(float2*)(p0 + 8 * NSEQ) = make_float2(acc[mt][nt][2], acc[mt][nt][3]);
        }
#undef K2_LOAD
}

// ---------------------------------------------------------------------------
// Kernel 3: LN over channels + @w_out + b_out (mma.sync split), * g -> out.
// A = Xn[p][c] via trans-ldsm of channel-major tile; B = w_out^T via trans.
// ---------------------------------------------------------------------------
__global__ void __launch_bounds__(256, 1)
k3_mma(const float* __restrict__ ln_s, const float* __restrict__ ln_b,
       const float* __restrict__ w_out, const float* __restrict__ b_out,
       float* __restrict__ out)
{
    extern __shared__ char smraw[];
    float* Xs = (float*)smraw;                       // [c][p] pitch 128
    __nv_bfloat16* Xnh = (__nv_bfloat16*)(Xs + 16384);  // [c][p] pitch 136
    __nv_bfloat16* Xnl = Xnh + 128 * PIT;
    __nv_bfloat16* Wh  = Xnl + 128 * PIT;            // [k][n] pitch 136
    __nv_bfloat16* Wl  = Wh + 128 * PIT;
    float* so   = (float*)(Wl + 128 * PIT);
    float* bo   = so + 128;
    float* bou  = bo + 128;
    float* redS = bou + 128;     // 256
    float* redQ = redS + 256;    // 256
    float* mus  = redQ + 256;    // 128
    float* rss  = mus + 128;     // 128

    const int tid = threadIdx.x, lane = tid & 31, wid = tid >> 5;
    const int pix0 = blockIdx.x * 128;

    for (int u = tid; u < 4096; u += 256) {
        int c = u >> 5, q = u & 31;
        ((float4*)(Xs + c * 128))[q] =
            ((const float4*)(g_x + (size_t)c * NN + pix0))[q];
        float4 w = ((const float4*)w_out)[u];
        uint2 hv, lv;
        split4(w, hv, lv);
        *(uint2*)(&Wh[c * PIT + q * 4]) = hv;
        *(uint2*)(&Wl[c * PIT + q * 4]) = lv;
    }
    if (tid < 128) { so[tid] = ln_s[tid]; bo[tid] = ln_b[tid]; bou[tid] = b_out[tid]; }
    __syncthreads();

    // LN stats over c (two threads per pixel)
    const int p = tid & 127, half = tid >> 7;
    {
        float s = 0.f, ss = 0.f;
        for (int c = half * 64; c < half * 64 + 64; ++c) {
            float v = Xs[c * 128 + p];
            s += v; ss += v * v;
        }
        redS[tid] = s; redQ[tid] = ss;
    }
    __syncthreads();
    if (tid < 128) {
        float S = redS[tid] + redS[tid + 128];
        float Qv = redQ[tid] + redQ[tid + 128];
        float mu = S * 0.0078125f;
        mus[tid] = mu;
        rss[tid] = rsqrtf(Qv * 0.0078125f - mu * mu + 1e-5f);
    }
    __syncthreads();

    // normalize + split -> Xnh/Xnl [c][p]
    for (int u = tid; u < 4096; u += 256) {
        int c = u >> 5, p4 = (u & 31) * 4;
        float4 v = *(float4*)(Xs + c * 128 + p4);
        float4 m4 = *(float4*)(mus + p4);
        float4 r4 = *(float4*)(rss + p4);
        float sc = so[c], bb = bo[c];
        float4 xn;
        xn.x = (v.x - m4.x) * r4.x * sc + bb;
        xn.y = (v.y - m4.y) * r4.y * sc + bb;
        xn.z = (v.z - m4.z) * r4.z * sc + bb;
        xn.w = (v.w - m4.w) * r4.w * sc + bb;
        uint2 hv, lv;
        split4(xn, hv, lv);
        *(uint2*)(&Xnh[c * PIT + p4]) = hv;
        *(uint2*)(&Xnl[c * PIT + p4]) = lv;
    }
    __syncthreads();

    const int wm = wid & 1, wn = wid >> 1;
    const uint32_t xh = smem_u32(Xnh), xl = smem_u32(Xnl);
    const uint32_t wh = smem_u32(Wh), wl = smem_u32(Wl);

    float acc[4][4][4];
#pragma unroll
    for (int a = 0; a < 4; ++a)
#pragma unroll
        for (int b = 0; b < 4; ++b)
#pragma unroll
            for (int q = 0; q < 4; ++q) acc[a][b][q] = 0.f;

    // A trans (storage [c][p]): row c, col p ; B trans (storage [c][n]): row c, col n
    const int at_row = (lane & 7) + ((lane >> 4) << 3);
    const int at_col = ((lane >> 3) & 1) << 3;
    const int bt_row = (lane & 7) + (((lane >> 3) & 1) << 3);
    const int bt_col = (lane >> 4) << 3;

#pragma unroll
    for (int k16 = 0; k16 < 8; ++k16) {
        const int kb = k16 * 16;
        uint32_t bh[4][2], bl[4][2];
#pragma unroll
        for (int ng = 0; ng < 2; ++ng) {
            uint32_t r4[4];
            uint32_t boff = (uint32_t)((kb + bt_row) * PITB) +
                            (wn * 32 + ng * 16 + bt_col) * 2;
            ldsm4_t(wh + boff, r4);
            bh[ng*2][0] = r4[0]; bh[ng*2][1] = r4[1];
            bh[ng*2+1][0] = r4[2]; bh[ng*2+1][1] = r4[3];
            ldsm4_t(wl + boff, r4);
            bl[ng*2][0] = r4[0]; bl[ng*2][1] = r4[1];
            bl[ng*2+1][0] = r4[2]; bl[ng*2+1][1] = r4[3];
        }
        uint32_t ah[4][4], al[4][4];
#pragma unroll
        for (int mt = 0; mt < 4; ++mt) {
            uint32_t aoff = (uint32_t)((kb + at_row) * PITB) +
                            (wm * 64 + mt * 16 + at_col) * 2;
            ldsm4_t(xh + aoff, ah[mt]);
            ldsm4_t(xl + aoff, al[mt]);
        }
#pragma unroll
        for (int mt = 0; mt < 4; ++mt)
#pragma unroll
            for (int nt = 0; nt < 4; ++nt) {
                mma_bf16(acc[mt][nt], ah[mt], bh[nt]);
                mma_bf16(acc[mt][nt], ah[mt], bl[nt]);
                mma_bf16(acc[mt][nt], al[mt], bh[nt]);
            }
    }

    // epilogue: (acc + b_out) * g -> out[p][ch]
#pragma unroll
    for (int mt = 0; mt < 4; ++mt) {
        int p0 = pix0 + wm * 64 + mt * 16 + (lane >> 2);
#pragma unroll
        for (int nt = 0; nt < 4; ++nt) {
            int ch = wn * 32 + nt * 8 + (lane & 3) * 2;
            float b0 = bou[ch], b1 = bou[ch + 1];
            float2 g0 = *(const float2*)(g_g + (size_t)p0 * CDIM + ch);
            float2 g1 = *(const float2*)(g_g + (size_t)(p0 + 8) * CDIM + ch);
            float2 v0 = make_float2((acc[mt][nt][0] + b0) * g0.x,
                                    (acc[mt][nt][1] + b1) * g0.y);
            float2 v1 = make_float2((acc[mt][nt][2] + b0) * g1.x,
                                    (acc[mt][nt][3] + b1) * g1.y);
            *(float2*)(out + (size_t)p0 * CDIM + ch) = v0;
            *(float2*)(out + (size_t)(p0 + 8) * CDIM + ch) = v1;
        }
    }
}

// ---------------------------------------------------------------------------
extern "C" void kernel_launch(void* const* d_in, const int* in_sizes, int n_in,
                              void* d_out, int out_size)
{
    const float* z        = (const float*)d_in[0];
    const float* mask     = (const float*)d_in[1];
    const float* ln_in_s  = (const float*)d_in[2];
    const float* ln_in_b  = (const float*)d_in[3];
    const float* w_left   = (const float*)d_in[4];
    const float* b_left   = (const float*)d_in[5];
    const float* w_right  = (const float*)d_in[6];
    const float* b_right  = (const float*)d_in[7];
    const float* w_lgate  = (const float*)d_in[8];
    const float* b_lgate  = (const float*)d_in[9];
    const float* w_rgate  = (const float*)d_in[10];
    const float* b_rgate  = (const float*)d_in[11];
    const float* ln_out_s = (const float*)d_in[12];
    const float* ln_out_b = (const float*)d_in[13];
    const float* w_out    = (const float*)d_in[14];
    const float* b_out    = (const float*)d_in[15];
    const float* w_gate   = (const float*)d_in[16];
    const float* b_gate   = (const float*)d_in[17];
    float* out = (float*)d_out;

    const int smem1g = 6 * 128 * PIT * 2 + 3 * 128 * 4;      // 210432
    const int smem1p = 4 * 128 * PIT * 2 + 3 * 128 * 4;      // 140800
    const int smem2  = 2 * (int)K2S;                         // 131072
    const int smem3  = 16384 * 4 + 4 * 128 * PIT * 2 + (3 * 128 + 2 * 256 + 2 * 128) * 4;

    cudaFuncSetAttribute(k1_mma<true>,  cudaFuncAttributeMaxDynamicSharedMemorySize, smem1g);
    cudaFuncSetAttribute(k1_mma<false>, cudaFuncAttributeMaxDynamicSharedMemorySize, smem1p);
    cudaFuncSetAttribute(k2_mma,        cudaFuncAttributeMaxDynamicSharedMemorySize, smem2);
    cudaFuncSetAttribute(k3_mma,        cudaFuncAttributeMaxDynamicSharedMemorySize, smem3);

    k1_mma<true><<<dim3(NN / 128, 2), 256, smem1g>>>(
        z, mask, ln_in_s, ln_in_b,
        w_lgate, b_lgate, w_left, b_left,
        w_rgate, b_rgate, w_right, b_right);

    k1_mma<false><<<dim3(NN / 128, 1), 256, smem1p>>>(
        z, mask, ln_in_s, ln_in_b,
        w_gate, b_gate, nullptr, nullptr,
        nullptr, nullptr, nullptr, nullptr);

    k2_mma<<<dim3(NSEQ / 128, NSEQ / 128, CDIM), 256, smem2>>>();

    k3_mma<<<dim3(NN / 128, 1), 256, smem3>>>(ln_out_s, ln_out_b, w_out, b_out, out);
}

// round 5
// speedup vs baseline: 2.4029x; 1.2807x over previous
#include <cuda_runtime.h>
#include <cuda_bf16.h>
#include <math.h>
#include <stddef.h>
#include <stdint.h>

// Triangle multiplicative update (outgoing), N=512, cz=ch=128, fp32 in/out.
// All GEMMs on tensor cores via mma.sync bf16 hi/lo split (3 passes, fp32 acc).
// Round 5: 512 threads / 16 warps per CTA to cover latency (was 256/8).

#define NSEQ 512
#define CDIM 128
#define NN   (NSEQ*NSEQ)          // 262144
#define PIT  136                  // bf16 smem pitch (elements)
#define PITB 272                  // bytes
#define NT   512                  // threads per CTA

__device__ __nv_bfloat16 g_a_hi[(size_t)CDIM * NN];
__device__ __nv_bfloat16 g_a_lo[(size_t)CDIM * NN];
__device__ __nv_bfloat16 g_b_hi[(size_t)CDIM * NN];
__device__ __nv_bfloat16 g_b_lo[(size_t)CDIM * NN];
__device__ float g_g[(size_t)NN * CDIM];   // g[pix][c]
__device__ float g_x[(size_t)CDIM * NN];   // xT[c][i][j]

__device__ __forceinline__ float sigmf(float x) {
    return 1.0f / (1.0f + __expf(-x));
}
__device__ __forceinline__ unsigned pk_bf16x2(float a, float b) {
    __nv_bfloat162 t = __floats2bfloat162_rn(a, b);
    return *reinterpret_cast<unsigned*>(&t);
}
__device__ __forceinline__ float bf16_res(float v) {   // v - bf16(v)
    return v - __bfloat162float(__float2bfloat16(v));
}
__device__ __forceinline__ uint32_t smem_u32(const void* p) {
    uint32_t a;
    asm("{ .reg .u64 t; cvta.to.shared.u64 t, %1; cvt.u32.u64 %0, t; }"
        : "=r"(a) : "l"(p));
    return a;
}
__device__ __forceinline__ void cp16(uint32_t dst, const void* src) {
    asm volatile("cp.async.cg.shared.global [%0], [%1], 16;"
                 :: "r"(dst), "l"(src) : "memory");
}
#define SWZ(o) ((o) ^ (((o) >> 3) & 0x70))

__device__ __forceinline__ void ldsm4(uint32_t addr, uint32_t* r) {
    asm volatile("ldmatrix.sync.aligned.m8n8.x4.shared.b16 {%0,%1,%2,%3}, [%4];"
                 : "=r"(r[0]), "=r"(r[1]), "=r"(r[2]), "=r"(r[3]) : "r"(addr));
}
__device__ __forceinline__ void ldsm4_t(uint32_t addr, uint32_t* r) {
    asm volatile("ldmatrix.sync.aligned.m8n8.x4.trans.shared.b16 {%0,%1,%2,%3}, [%4];"
                 : "=r"(r[0]), "=r"(r[1]), "=r"(r[2]), "=r"(r[3]) : "r"(addr));
}
__device__ __forceinline__ void mma_bf16(float* c, const uint32_t* a,
                                         const uint32_t* b) {
    asm volatile(
        "mma.sync.aligned.m16n8k16.row.col.f32.bf16.bf16.f32 "
        "{%0,%1,%2,%3}, {%4,%5,%6,%7}, {%8,%9}, {%0,%1,%2,%3};"
        : "+f"(c[0]), "+f"(c[1]), "+f"(c[2]), "+f"(c[3])
        : "r"(a[0]), "r"(a[1]), "r"(a[2]), "r"(a[3]), "r"(b[0]), "r"(b[1]));
}

__device__ __forceinline__ void split4(float4 v, uint2& hv, uint2& lv) {
    hv.x = pk_bf16x2(v.x, v.y);
    hv.y = pk_bf16x2(v.z, v.w);
    lv.x = pk_bf16x2(bf16_res(v.x), bf16_res(v.y));
    lv.y = pk_bf16x2(bf16_res(v.z), bf16_res(v.w));
}

// ---------------------------------------------------------------------------
// Kernel 1: fused LayerNorm + projection via mma.sync (split bf16).
// 16 warps: 4 (M) x 4 (N); warp tile 32x32 (mt<2 of m16, nt<4 of n8).
// ---------------------------------------------------------------------------
template <bool GATED>
__global__ void __launch_bounds__(NT, 1)
k1_mma(const float* __restrict__ z, const float* __restrict__ mask,
       const float* __restrict__ ln_s, const float* __restrict__ ln_b,
       const float* __restrict__ Wg0, const float* __restrict__ bg0,
       const float* __restrict__ Wv0, const float* __restrict__ bv0,
       const float* __restrict__ Wg1, const float* __restrict__ bg1,
       const float* __restrict__ Wv1, const float* __restrict__ bv1)
{
    extern __shared__ char smraw[];
    __nv_bfloat16* znh = (__nv_bfloat16*)smraw;           // [p][k] pitch 136
    __nv_bfloat16* znl = znh + 128 * PIT;
    __nv_bfloat16* Wgh = znl + 128 * PIT;                 // [k][n] pitch 136
    __nv_bfloat16* Wgl = Wgh + 128 * PIT;
    __nv_bfloat16* Wvh = Wgl + 128 * PIT;                 // gated only
    __nv_bfloat16* Wvl = Wvh + 128 * PIT;
    float* bgs = (float*)(GATED ? (void*)(Wvl + 128 * PIT)
                                : (void*)(Wgl + 128 * PIT));
    float* bvs = bgs + 128;
    float* msm = bvs + 128;

    const int tid = threadIdx.x, lane = tid & 31, wid = tid >> 5;
    const int pix0 = blockIdx.x * 128;

    const float *Wgp, *bgp, *Wvp = nullptr, *bvp = nullptr;
    if (GATED) {
        if (blockIdx.y == 0) { Wgp = Wg0; bgp = bg0; Wvp = Wv0; bvp = bv0; }
        else                 { Wgp = Wg1; bgp = bg1; Wvp = Wv1; bvp = bv1; }
    } else {
        Wgp = Wg0; bgp = bg0;
    }

    if (tid < 128) {
        bgs[tid] = bgp[tid];
        if (GATED) { bvs[tid] = bvp[tid]; msm[tid] = mask[pix0 + tid]; }
    }

    // load + hi/lo split weights into smem
    for (int u = tid; u < 4096; u += NT) {
        int k = u >> 5, n4 = (u & 31) * 4;
        float4 w = ((const float4*)Wgp)[u];
        uint2 hv, lv;
        split4(w, hv, lv);
        *(uint2*)(&Wgh[k * PIT + n4]) = hv;
        *(uint2*)(&Wgl[k * PIT + n4]) = lv;
        if (GATED) {
            float4 w2 = ((const float4*)Wvp)[u];
            split4(w2, hv, lv);
            *(uint2*)(&Wvh[k * PIT + n4]) = hv;
            *(uint2*)(&Wvl[k * PIT + n4]) = lv;
        }
    }

    // LayerNorm -> split zn into smem (one warp per row, 8 rows each)
    {
        float4 s4 = ((const float4*)ln_s)[lane];
        float4 b4 = ((const float4*)ln_b)[lane];
        for (int r = wid; r < 128; r += 16) {
            float4 v = ((const float4*)(z + (size_t)(pix0 + r) * CDIM))[lane];
            float s  = v.x + v.y + v.z + v.w;
            float ss = v.x*v.x + v.y*v.y + v.z*v.z + v.w*v.w;
#pragma unroll
            for (int o = 16; o > 0; o >>= 1) {
                s  += __shfl_xor_sync(0xffffffffu, s,  o);
                ss += __shfl_xor_sync(0xffffffffu, ss, o);
            }
            float mu   = s * 0.0078125f;
            float rstd = rsqrtf(ss * 0.0078125f - mu * mu + 1e-5f);
            float4 o4;
            o4.x = (v.x - mu) * rstd * s4.x + b4.x;
            o4.y = (v.y - mu) * rstd * s4.y + b4.y;
            o4.z = (v.z - mu) * rstd * s4.z + b4.z;
            o4.w = (v.w - mu) * rstd * s4.w + b4.w;
            uint2 hv, lv;
            split4(o4, hv, lv);
            *(uint2*)(&znh[r * PIT + lane * 4]) = hv;
            *(uint2*)(&znl[r * PIT + lane * 4]) = lv;
        }
    }
    __syncthreads();

    const int wm = wid & 3, wn = wid >> 2;   // 4 (M) x 4 (N) warp grid
    const uint32_t zh = smem_u32(znh), zl = smem_u32(znl);
    const uint32_t wgh = smem_u32(Wgh), wgl = smem_u32(Wgl);
    const uint32_t wvh = GATED ? smem_u32(Wvh) : 0;
    const uint32_t wvl = GATED ? smem_u32(Wvl) : 0;

    float P[2][4][4], Q[2][4][4];
#pragma unroll
    for (int a = 0; a < 2; ++a)
#pragma unroll
        for (int b = 0; b < 4; ++b)
#pragma unroll
            for (int q = 0; q < 4; ++q) { P[a][b][q] = 0.f; if (GATED) Q[a][b][q] = 0.f; }

    if (GATED) {
        // A = W^T (trans): row k, col ch ; B = zn (non-trans): row p
        const int at_row = (lane & 7) + ((lane >> 4) << 3);
        const int at_col = ((lane >> 3) & 1) << 3;
        const int bp_row = wn * 32 + (lane & 7) + ((lane >> 4) << 3);
        const uint32_t bko = ((lane >> 3) & 1) * 16;

#pragma unroll
        for (int k16 = 0; k16 < 8; ++k16) {
            const int kb = k16 * 16;
            uint32_t bh[4][2], bl[4][2];
#pragma unroll
            for (int ng = 0; ng < 2; ++ng) {
                uint32_t r4[4];
                uint32_t boff = (uint32_t)((bp_row + ng * 16) * PITB) + kb * 2 + bko;
                ldsm4(zh + boff, r4);
                bh[ng*2][0] = r4[0]; bh[ng*2][1] = r4[1];
                bh[ng*2+1][0] = r4[2]; bh[ng*2+1][1] = r4[3];
                ldsm4(zl + boff, r4);
                bl[ng*2][0] = r4[0]; bl[ng*2][1] = r4[1];
                bl[ng*2+1][0] = r4[2]; bl[ng*2+1][1] = r4[3];
            }
            uint32_t aoff[2];
#pragma unroll
            for (int mt = 0; mt < 2; ++mt)
                aoff[mt] = (uint32_t)((kb + at_row) * PITB) +
                           (wm * 32 + mt * 16 + at_col) * 2;
            uint32_t a[2][4];
#pragma unroll
            for (int mt = 0; mt < 2; ++mt) ldsm4_t(wgh + aoff[mt], a[mt]);
#pragma unroll
            for (int mt = 0; mt < 2; ++mt)
#pragma unroll
                for (int nt = 0; nt < 4; ++nt) {
                    mma_bf16(P[mt][nt], a[mt], bh[nt]);
                    mma_bf16(P[mt][nt], a[mt], bl[nt]);
                }
#pragma unroll
            for (int mt = 0; mt < 2; ++mt) ldsm4_t(wgl + aoff[mt], a[mt]);
#pragma unroll
            for (int mt = 0; mt < 2; ++mt)
#pragma unroll
                for (int nt = 0; nt < 4; ++nt)
                    mma_bf16(P[mt][nt], a[mt], bh[nt]);
#pragma unroll
            for (int mt = 0; mt < 2; ++mt) ldsm4_t(wvh + aoff[mt], a[mt]);
#pragma unroll
            for (int mt = 0; mt < 2; ++mt)
#pragma unroll
                for (int nt = 0; nt < 4; ++nt) {
                    mma_bf16(Q[mt][nt], a[mt], bh[nt]);
                    mma_bf16(Q[mt][nt], a[mt], bl[nt]);
                }
#pragma unroll
            for (int mt = 0; mt < 2; ++mt) ldsm4_t(wvl + aoff[mt], a[mt]);
#pragma unroll
            for (int mt = 0; mt < 2; ++mt)
#pragma unroll
                for (int nt = 0; nt < 4; ++nt)
                    mma_bf16(Q[mt][nt], a[mt], bh[nt]);
        }

        // epilogue: mask * sig(P + bg) * (Q + bv) -> channel-major hi/lo
        __nv_bfloat16* oh = (blockIdx.y == 0) ? g_a_hi : g_b_hi;
        __nv_bfloat16* ol = (blockIdx.y == 0) ? g_a_lo : g_b_lo;
#pragma unroll
        for (int mt = 0; mt < 2; ++mt) {
            int ch = wm * 32 + mt * 16 + (lane >> 2);
            float bg0 = bgs[ch], bg1 = bgs[ch + 8];
            float bv0 = bvs[ch], bv1 = bvs[ch + 8];
            size_t r0 = (size_t)ch * NN + pix0;
            size_t r1 = (size_t)(ch + 8) * NN + pix0;
#pragma unroll
            for (int nt = 0; nt < 4; ++nt) {
                int p = wn * 32 + nt * 8 + (lane & 3) * 2;
                float m0 = msm[p], m1 = msm[p + 1];
                float v00 = m0 * sigmf(P[mt][nt][0] + bg0) * (Q[mt][nt][0] + bv0);
                float v01 = m1 * sigmf(P[mt][nt][1] + bg0) * (Q[mt][nt][1] + bv0);
                float v10 = m0 * sigmf(P[mt][nt][2] + bg1) * (Q[mt][nt][2] + bv1);
                float v11 = m1 * sigmf(P[mt][nt][3] + bg1) * (Q[mt][nt][3] + bv1);
                *(uint32_t*)(oh + r0 + p) = pk_bf16x2(v00, v01);
                *(uint32_t*)(ol + r0 + p) = pk_bf16x2(bf16_res(v00), bf16_res(v01));
                *(uint32_t*)(oh + r1 + p) = pk_bf16x2(v10, v11);
                *(uint32_t*)(ol + r1 + p) = pk_bf16x2(bf16_res(v10), bf16_res(v11));
            }
        }
    } else {
        // A = zn (non-trans): row p ; B = W^T (trans): row k, col ch
        const int a_row = wm * 32 + (lane & 15);
        const uint32_t ako = (lane >> 4) * 16;
        const int bt_row = (lane & 7) + (((lane >> 3) & 1) << 3);
        const int bt_col = (lane >> 4) << 3;

#pragma unroll
        for (int k16 = 0; k16 < 8; ++k16) {
            const int kb = k16 * 16;
            uint32_t bh[4][2], bl[4][2];
#pragma unroll
            for (int ng = 0; ng < 2; ++ng) {
                uint32_t r4[4];
                uint32_t boff = (uint32_t)((kb + bt_row) * PITB) +
                                (wn * 32 + ng * 16 + bt_col) * 2;
                ldsm4_t(wgh + boff, r4);
                bh[ng*2][0] = r4[0]; bh[ng*2][1] = r4[1];
                bh[ng*2+1][0] = r4[2]; bh[ng*2+1][1] = r4[3];
                ldsm4_t(wgl + boff, r4);
                bl[ng*2][0] = r4[0]; bl[ng*2][1] = r4[1];
                bl[ng*2+1][0] = r4[2]; bl[ng*2+1][1] = r4[3];
            }
            uint32_t ah[2][4], al[2][4];
#pragma unroll
            for (int mt = 0; mt < 2; ++mt) {
                uint32_t aoff = (uint32_t)((a_row + mt * 16) * PITB) + kb * 2 + ako;
                ldsm4(zh + aoff, ah[mt]);
                ldsm4(zl + aoff, al[mt]);
            }
#pragma unroll
            for (int mt = 0; mt < 2; ++mt)
#pragma unroll
                for (int nt = 0; nt < 4; ++nt) {
                    mma_bf16(P[mt][nt], ah[mt], bh[nt]);
                    mma_bf16(P[mt][nt], ah[mt], bl[nt]);
                    mma_bf16(P[mt][nt], al[mt], bh[nt]);
                }
        }

        // epilogue: sigmoid -> g_g[p][ch]
#pragma unroll
        for (int mt = 0; mt < 2; ++mt) {
            int p0 = pix0 + wm * 32 + mt * 16 + (lane >> 2);
#pragma unroll
            for (int nt = 0; nt < 4; ++nt) {
                int ch = wn * 32 + nt * 8 + (lane & 3) * 2;
                float b0 = bgs[ch], b1 = bgs[ch + 1];
                float2 v0 = make_float2(sigmf(P[mt][nt][0] + b0),
                                        sigmf(P[mt][nt][1] + b1));
                float2 v1 = make_float2(sigmf(P[mt][nt][2] + b0),
                                        sigmf(P[mt][nt][3] + b1));
                *(float2*)(g_g + (size_t)p0 * CDIM + ch) = v0;
                *(float2*)(g_g + (size_t)(p0 + 8) * CDIM + ch) = v1;
            }
        }
    }
}

// ---------------------------------------------------------------------------
// Kernel 2: per-channel X_c = A_c @ B_c^T via mma.sync bf16 hi/lo split.
// 16 warps: 4 (M) x 4 (N), warp tile 32x32.
// ---------------------------------------------------------------------------
#define K2S 65536u

__global__ void __launch_bounds__(NT, 1)
k2_mma()
{
    extern __shared__ char sm2[];
    const uint32_t smb = smem_u32(sm2);
    const int tid  = threadIdx.x;
    const int lane = tid & 31, wid = tid >> 5;
    const int wm = wid & 3, wn = wid >> 2;
    const int i0 = blockIdx.x * 128, j0 = blockIdx.y * 128;
    const size_t cbase = (size_t)blockIdx.z * NN;

    const __nv_bfloat16* Ah = g_a_hi + cbase + (size_t)i0 * NSEQ;
    const __nv_bfloat16* Al = g_a_lo + cbase + (size_t)i0 * NSEQ;
    const __nv_bfloat16* Bh = g_b_hi + cbase + (size_t)j0 * NSEQ;
    const __nv_bfloat16* Bl = g_b_lo + cbase + (size_t)j0 * NSEQ;

    float acc[2][4][4];
#pragma unroll
    for (int mt = 0; mt < 2; ++mt)
#pragma unroll
        for (int nt = 0; nt < 4; ++nt)
#pragma unroll
            for (int q = 0; q < 4; ++q) acc[mt][nt][q] = 0.f;

    const int arow = wm * 32 + (lane & 15);
    const int bnr  = wn * 32 + (lane & 7) + ((lane >> 4) << 3);
    const uint32_t a_koff = (uint32_t)((lane >> 4) << 4);
    const uint32_t b_koff = (uint32_t)(((lane >> 3) & 1) << 4);

#define K2_LOAD(kc, stg)                                                      \
    do {                                                                      \
        const int ke = (kc) * 64;                                             \
        _Pragma("unroll")                                                     \
        for (int t = 0; t < 2; ++t) {                                         \
            int v = tid + t * NT; int r = v >> 3, cu = v & 7;                 \
            uint32_t so = SWZ((uint32_t)(r * 128 + cu * 16));                 \
            const size_t go = (size_t)r * NSEQ + ke + cu * 8;                 \
            cp16((stg) + so,           Ah + go);                              \
            cp16((stg) + 16384u + so,  Al + go);                              \
            cp16((stg) + 32768u + so,  Bh + go);                              \
            cp16((stg) + 49152u + so,  Bl + go);                              \
        }                                                                     \
        asm volatile("cp.async.commit_group;" ::: "memory");                  \
    } while (0)

    K2_LOAD(0, smb);

    for (int kc = 0; kc < 8; ++kc) {
        const uint32_t stg = smb + (uint32_t)(kc & 1) * K2S;
        if (kc < 7) K2_LOAD(kc + 1, smb + (uint32_t)((kc + 1) & 1) * K2S);
        if (kc < 7) asm volatile("cp.async.wait_group 1;" ::: "memory");
        else        asm volatile("cp.async.wait_group 0;" ::: "memory");
        __syncthreads();

#pragma unroll
        for (int k16 = 0; k16 < 4; ++k16) {
            const uint32_t kbA = (uint32_t)(k16 * 32) + a_koff;
            const uint32_t kbB = (uint32_t)(k16 * 32) + b_koff;
            uint32_t bh[4][2], bl[4][2];
#pragma unroll
            for (int ng = 0; ng < 2; ++ng) {
                uint32_t r4[4];
                uint32_t off = SWZ((uint32_t)((bnr + ng * 16) * 128) + kbB);
                ldsm4(stg + 32768u + off, r4);
                bh[ng * 2 + 0][0] = r4[0]; bh[ng * 2 + 0][1] = r4[1];
                bh[ng * 2 + 1][0] = r4[2]; bh[ng * 2 + 1][1] = r4[3];
                ldsm4(stg + 49152u + off, r4);
                bl[ng * 2 + 0][0] = r4[0]; bl[ng * 2 + 0][1] = r4[1];
                bl[ng * 2 + 1][0] = r4[2]; bl[ng * 2 + 1][1] = r4[3];
            }
#pragma unroll
            for (int mt = 0; mt < 2; ++mt) {
                uint32_t ah[4], al[4];
                uint32_t off = SWZ((uint32_t)((arow + mt * 16) * 128) + kbA);
                ldsm4(stg + off, ah);
                ldsm4(stg + 16384u + off, al);
#pragma unroll
                for (int nt = 0; nt < 4; ++nt) {
                    mma_bf16(acc[mt][nt], ah, bh[nt]);
                    mma_bf16(acc[mt][nt], ah, bl[nt]);
                    mma_bf16(acc[mt][nt], al, bh[nt]);
                }
            }
        }
        __syncthreads();
    }

    float* Xg = g_x + cbase + (size_t)(i0 + wm * 32) * NSEQ + j0 + wn * 32;
    const int rr = lane >> 2, cc = (lane & 3) * 2;
#pragma unroll
    for (int mt = 0; mt < 2; ++mt)
#pragma unroll
        for (int nt = 0; nt < 4; ++nt) {
            float* p0 = Xg + (size_t)(mt * 16 + rr) * NSEQ + nt * 8 + cc;
            *(float2*)p0              = make_float2(acc[mt][nt][0], acc[mt][nt][1]);
            *(float2*)(p0 + 8 * NSEQ) = make_float2(acc[mt][nt][2], acc[mt][nt][3]);
        }
#undef K2_LOAD
}

// ---------------------------------------------------------------------------
// Kernel 3: LN over channels + @w_out + b_out (mma.sync split), * g -> out.
// ---------------------------------------------------------------------------
__global__ void __launch_bounds__(NT, 1)
k3_mma(const float* __restrict__ ln_s, const float* __restrict__ ln_b,
       const float* __restrict__ w_out, const float* __restrict__ b_out,
       float* __restrict__ out)
{
    extern __shared__ char smraw[];
    float* Xs = (float*)smraw;                          // [c][p] pitch 128
    __nv_bfloat16* Xnh = (__nv_bfloat16*)(Xs + 16384);  // [c][p] pitch 136
    __nv_bfloat16* Xnl = Xnh + 128 * PIT;
    __nv_bfloat16* Wh  = Xnl + 128 * PIT;               // [k][n] pitch 136
    __nv_bfloat16* Wl  = Wh + 128 * PIT;
    float* so   = (float*)(Wl + 128 * PIT);
    float* bo   = so + 128;
    float* bou  = bo + 128;
    float* redS = bou + 128;     // 512
    float* redQ = redS + 512;    // 512
    float* mus  = redQ + 512;    // 128
    float* rss  = mus + 128;     // 128

    const int tid = threadIdx.x, lane = tid & 31, wid = tid >> 5;
    const int pix0 = blockIdx.x * 128;

    for (int u = tid; u < 4096; u += NT) {
        int c = u >> 5, q = u & 31;
        ((float4*)(Xs + c * 128))[q] =
            ((const float4*)(g_x + (size_t)c * NN + pix0))[q];
        float4 w = ((const float4*)w_out)[u];
        uint2 hv, lv;
        split4(w, hv, lv);
        *(uint2*)(&Wh[c * PIT + q * 4]) = hv;
        *(uint2*)(&Wl[c * PIT + q * 4]) = lv;
    }
    if (tid < 128) { so[tid] = ln_s[tid]; bo[tid] = ln_b[tid]; bou[tid] = b_out[tid]; }
    __syncthreads();

    // LN stats over c (four threads per pixel, 32 channels each)
    const int p = tid & 127, quarter = tid >> 7;
    {
        float s = 0.f, ss = 0.f;
        for (int c = quarter * 32; c < quarter * 32 + 32; ++c) {
            float v = Xs[c * 128 + p];
            s += v; ss += v * v;
        }
        redS[tid] = s; redQ[tid] = ss;
    }
    __syncthreads();
    if (tid < 128) {
        float S  = redS[tid] + redS[tid + 128] + redS[tid + 256] + redS[tid + 384];
        float Qv = redQ[tid] + redQ[tid + 128] + redQ[tid + 256] + redQ[tid + 384];
        float mu = S * 0.0078125f;
        mus[tid] = mu;
        rss[tid] = rsqrtf(Qv * 0.0078125f - mu * mu + 1e-5f);
    }
    __syncthreads();

    // normalize + split -> Xnh/Xnl [c][p]
    for (int u = tid; u < 4096; u += NT) {
        int c = u >> 5, p4 = (u & 31) * 4;
        float4 v = *(float4*)(Xs + c * 128 + p4);
        float4 m4 = *(float4*)(mus + p4);
        float4 r4 = *(float4*)(rss + p4);
        float sc = so[c], bb = bo[c];
        float4 xn;
        xn.x = (v.x - m4.x) * r4.x * sc + bb;
        xn.y = (v.y - m4.y) * r4.y * sc + bb;
        xn.z = (v.z - m4.z) * r4.z * sc + bb;
        xn.w = (v.w - m4.w) * r4.w * sc + bb;
        uint2 hv, lv;
        split4(xn, hv, lv);
        *(uint2*)(&Xnh[c * PIT + p4]) = hv;
        *(uint2*)(&Xnl[c * PIT + p4]) = lv;
    }
    __syncthreads();

    const int wm = wid & 3, wn = wid >> 2;
    const uint32_t xh = smem_u32(Xnh), xl = smem_u32(Xnl);
    const uint32_t wh = smem_u32(Wh), wl = smem_u32(Wl);

    float acc[2][4][4];
#pragma unroll
    for (int a = 0; a < 2; ++a)
#pragma unroll
        for (int b = 0; b < 4; ++b)
#pragma unroll
            for (int q = 0; q < 4; ++q) acc[a][b][q] = 0.f;

    const int at_row = (lane & 7) + ((lane >> 4) << 3);
    const int at_col = ((lane >> 3) & 1) << 3;
    const int bt_row = (lane & 7) + (((lane >> 3) & 1) << 3);
    const int bt_col = (lane >> 4) << 3;

#pragma unroll
    for (int k16 = 0; k16 < 8; ++k16) {
        const int kb = k16 * 16;
        uint32_t bh[4][2], bl[4][2];
#pragma unroll
        for (int ng = 0; ng < 2; ++ng) {
            uint32_t r4[4];
            uint32_t boff = (uint32_t)((kb + bt_row) * PITB) +
                            (wn * 32 + ng * 16 + bt_col) * 2;
            ldsm4_t(wh + boff, r4);
            bh[ng*2][0] = r4[0]; bh[ng*2][1] = r4[1];
            bh[ng*2+1][0] = r4[2]; bh[ng*2+1][1] = r4[3];
            ldsm4_t(wl + boff, r4);
            bl[ng*2][0] = r4[0]; bl[ng*2][1] = r4[1];
            bl[ng*2+1][0] = r4[2]; bl[ng*2+1][1] = r4[3];
        }
        uint32_t ah[2][4], al[2][4];
#pragma unroll
        for (int mt = 0; mt < 2; ++mt) {
            uint32_t aoff = (uint32_t)((kb + at_row) * PITB) +
                            (wm * 32 + mt * 16 + at_col) * 2;
            ldsm4_t(xh + aoff, ah[mt]);
            ldsm4_t(xl + aoff, al[mt]);
        }
#pragma unroll
        for (int mt = 0; mt < 2; ++mt)
#pragma unroll
            for (int nt = 0; nt < 4; ++nt) {
                mma_bf16(acc[mt][nt], ah[mt], bh[nt]);
                mma_bf16(acc[mt][nt], ah[mt], bl[nt]);
                mma_bf16(acc[mt][nt], al[mt], bh[nt]);
            }
    }

    // epilogue: (acc + b_out) * g -> out[p][ch]
#pragma unroll
    for (int mt = 0; mt < 2; ++mt) {
        int p0 = pix0 + wm * 32 + mt * 16 + (lane >> 2);
#pragma unroll
        for (int nt = 0; nt < 4; ++nt) {
            int ch = wn * 32 + nt * 8 + (lane & 3) * 2;
            float b0 = bou[ch], b1 = bou[ch + 1];
            float2 g0 = *(const float2*)(g_g + (size_t)p0 * CDIM + ch);
            float2 g1 = *(const float2*)(g_g + (size_t)(p0 + 8) * CDIM + ch);
            float2 v0 = make_float2((acc[mt][nt][0] + b0) * g0.x,
                                    (acc[mt][nt][1] + b1) * g0.y);
            float2 v1 = make_float2((acc[mt][nt][2] + b0) * g1.x,
                                    (acc[mt][nt][3] + b1) * g1.y);
            *(float2*)(out + (size_t)p0 * CDIM + ch) = v0;
            *(float2*)(out + (size_t)(p0 + 8) * CDIM + ch) = v1;
        }
    }
}

// ---------------------------------------------------------------------------
extern "C" void kernel_launch(void* const* d_in, const int* in_sizes, int n_in,
                              void* d_out, int out_size)
{
    const float* z        = (const float*)d_in[0];
    const float* mask     = (const float*)d_in[1];
    const float* ln_in_s  = (const float*)d_in[2];
    const float* ln_in_b  = (const float*)d_in[3];
    const float* w_left   = (const float*)d_in[4];
    const float* b_left   = (const float*)d_in[5];
    const float* w_right  = (const float*)d_in[6];
    const float* b_right  = (const float*)d_in[7];
    const float* w_lgate  = (const float*)d_in[8];
    const float* b_lgate  = (const float*)d_in[9];
    const float* w_rgate  = (const float*)d_in[10];
    const float* b_rgate  = (const float*)d_in[11];
    const float* ln_out_s = (const float*)d_in[12];
    const float* ln_out_b = (const float*)d_in[13];
    const float* w_out    = (const float*)d_in[14];
    const float* b_out    = (const float*)d_in[15];
    const float* w_gate   = (const float*)d_in[16];
    const float* b_gate   = (const float*)d_in[17];
    float* out = (float*)d_out;

    const int smem1g = 6 * 128 * PIT * 2 + 3 * 128 * 4;      // 210432
    const int smem1p = 4 * 128 * PIT * 2 + 3 * 128 * 4;      // 140800
    const int smem2  = 2 * (int)K2S;                         // 131072
    const int smem3  = 16384 * 4 + 4 * 128 * PIT * 2 +
                       (3 * 128 + 2 * 512 + 2 * 128) * 4;    // ~212k

    cudaFuncSetAttribute(k1_mma<true>,  cudaFuncAttributeMaxDynamicSharedMemorySize, smem1g);
    cudaFuncSetAttribute(k1_mma<false>, cudaFuncAttributeMaxDynamicSharedMemorySize, smem1p);
    cudaFuncSetAttribute(k2_mma,        cudaFuncAttributeMaxDynamicSharedMemorySize, smem2);
    cudaFuncSetAttribute(k3_mma,        cudaFuncAttributeMaxDynamicSharedMemorySize, smem3);

    k1_mma<true><<<dim3(NN / 128, 2), NT, smem1g>>>(
        z, mask, ln_in_s, ln_in_b,
        w_lgate, b_lgate, w_left, b_left,
        w_rgate, b_rgate, w_right, b_right);

    k1_mma<false><<<dim3(NN / 128, 1), NT, smem1p>>>(
        z, mask, ln_in_s, ln_in_b,
        w_gate, b_gate, nullptr, nullptr,
        nullptr, nullptr, nullptr, nullptr);

    k2_mma<<<dim3(NSEQ / 128, NSEQ / 128, CDIM), NT, smem2>>>();

    k3_mma<<<dim3(NN / 128, 1), NT, smem3>>>(ln_out_s, ln_out_b, w_out, b_out, out);
}

// round 6
// speedup vs baseline: 2.9497x; 1.2275x over previous
#include <cuda_runtime.h>
#include <cuda_bf16.h>
#include <math.h>
#include <stddef.h>
#include <stdint.h>

// Triangle multiplicative update (outgoing), N=512, cz=ch=128, fp32 in/out.
// All GEMMs on tensor cores via mma.sync bf16 hi/lo split (3 passes, fp32 acc).
// Round 6: pre-split weights (k0), cp.async staging overlapped with LN.

#define NSEQ 512
#define CDIM 128
#define NN   (NSEQ*NSEQ)          // 262144
#define PIT  136                  // bf16 smem pitch (elements)
#define PITB 272                  // bytes
#define NT   512                  // threads per CTA

__device__ __nv_bfloat16 g_a_hi[(size_t)CDIM * NN];
__device__ __nv_bfloat16 g_a_lo[(size_t)CDIM * NN];
__device__ __nv_bfloat16 g_b_hi[(size_t)CDIM * NN];
__device__ __nv_bfloat16 g_b_lo[(size_t)CDIM * NN];
__device__ float g_g[(size_t)NN * CDIM];   // g[pix][c]
__device__ float g_x[(size_t)CDIM * NN];   // xT[c][i][j]
// pre-split weights: 0=lgate 1=left 2=rgate 3=right 4=gate 5=out
__device__ __align__(16) __nv_bfloat16 g_wh[6 * 16384];
__device__ __align__(16) __nv_bfloat16 g_wl[6 * 16384];

__device__ __forceinline__ float sigmf(float x) {
    return 1.0f / (1.0f + __expf(-x));
}
__device__ __forceinline__ unsigned pk_bf16x2(float a, float b) {
    __nv_bfloat162 t = __floats2bfloat162_rn(a, b);
    return *reinterpret_cast<unsigned*>(&t);
}
__device__ __forceinline__ float bf16_res(float v) {   // v - bf16(v)
    return v - __bfloat162float(__float2bfloat16(v));
}
__device__ __forceinline__ uint32_t smem_u32(const void* p) {
    uint32_t a;
    asm("{ .reg .u64 t; cvta.to.shared.u64 t, %1; cvt.u32.u64 %0, t; }"
        : "=r"(a) : "l"(p));
    return a;
}
__device__ __forceinline__ void cp16(uint32_t dst, const void* src) {
    asm volatile("cp.async.cg.shared.global [%0], [%1], 16;"
                 :: "r"(dst), "l"(src) : "memory");
}
#define CP_COMMIT() asm volatile("cp.async.commit_group;" ::: "memory")
#define CP_WAIT0()  asm volatile("cp.async.wait_group 0;" ::: "memory")
#define SWZ(o) ((o) ^ (((o) >> 3) & 0x70))

__device__ __forceinline__ void ldsm4(uint32_t addr, uint32_t* r) {
    asm volatile("ldmatrix.sync.aligned.m8n8.x4.shared.b16 {%0,%1,%2,%3}, [%4];"
                 : "=r"(r[0]), "=r"(r[1]), "=r"(r[2]), "=r"(r[3]) : "r"(addr));
}
__device__ __forceinline__ void ldsm4_t(uint32_t addr, uint32_t* r) {
    asm volatile("ldmatrix.sync.aligned.m8n8.x4.trans.shared.b16 {%0,%1,%2,%3}, [%4];"
                 : "=r"(r[0]), "=r"(r[1]), "=r"(r[2]), "=r"(r[3]) : "r"(addr));
}
__device__ __forceinline__ void mma_bf16(float* c, const uint32_t* a,
                                         const uint32_t* b) {
    asm volatile(
        "mma.sync.aligned.m16n8k16.row.col.f32.bf16.bf16.f32 "
        "{%0,%1,%2,%3}, {%4,%5,%6,%7}, {%8,%9}, {%0,%1,%2,%3};"
        : "+f"(c[0]), "+f"(c[1]), "+f"(c[2]), "+f"(c[3])
        : "r"(a[0]), "r"(a[1]), "r"(a[2]), "r"(a[3]), "r"(b[0]), "r"(b[1]));
}

__device__ __forceinline__ void split4(float4 v, uint2& hv, uint2& lv) {
    hv.x = pk_bf16x2(v.x, v.y);
    hv.y = pk_bf16x2(v.z, v.w);
    lv.x = pk_bf16x2(bf16_res(v.x), bf16_res(v.y));
    lv.y = pk_bf16x2(bf16_res(v.z), bf16_res(v.w));
}

// ---------------------------------------------------------------------------
// Kernel 0: pre-split the 6 weight matrices to bf16 hi/lo scratch.
// grid 96 x 256 threads, 4 floats per thread.
// ---------------------------------------------------------------------------
__global__ void __launch_bounds__(256)
k0_split(const float* __restrict__ w0, const float* __restrict__ w1,
         const float* __restrict__ w2, const float* __restrict__ w3,
         const float* __restrict__ w4, const float* __restrict__ w5)
{
    const float* ws[6] = {w0, w1, w2, w3, w4, w5};
    int idx = blockIdx.x * 256 + threadIdx.x;   // 24576 threads
    int m = idx >> 12;                          // matrix
    int e = (idx & 4095) * 4;                   // element
    float4 v = *(const float4*)(ws[m] + e);
    uint2 hv, lv;
    split4(v, hv, lv);
    *(uint2*)(g_wh + m * 16384 + e) = hv;
    *(uint2*)(g_wl + m * 16384 + e) = lv;
}

// ---------------------------------------------------------------------------
// Kernel 1: fused LayerNorm + projection via mma.sync (split bf16).
// Weights staged via cp.async from pre-split scratch, overlapped with LN.
// 16 warps: 4 (M) x 4 (N); warp tile 32x32.
// ---------------------------------------------------------------------------
template <bool GATED>
__global__ void __launch_bounds__(NT, 1)
k1_mma(const float* __restrict__ z, const float* __restrict__ mask,
       const float* __restrict__ ln_s, const float* __restrict__ ln_b,
       const float* __restrict__ bg0, const float* __restrict__ bv0,
       const float* __restrict__ bg1, const float* __restrict__ bv1)
{
    extern __shared__ char smraw[];
    __nv_bfloat16* znh = (__nv_bfloat16*)smraw;           // [p][k] pitch 136
    __nv_bfloat16* znl = znh + 128 * PIT;
    __nv_bfloat16* Wgh = znl + 128 * PIT;                 // [k][n] pitch 136
    __nv_bfloat16* Wgl = Wgh + 128 * PIT;
    __nv_bfloat16* Wvh = Wgl + 128 * PIT;                 // gated only
    __nv_bfloat16* Wvl = Wvh + 128 * PIT;
    float* bgs = (float*)(GATED ? (void*)(Wvl + 128 * PIT)
                                : (void*)(Wgl + 128 * PIT));
    float* bvs = bgs + 128;
    float* msm = bvs + 128;

    const int tid = threadIdx.x, lane = tid & 31, wid = tid >> 5;
    const int pix0 = blockIdx.x * 128;

    int mg, mv = 0;
    const float *bgp, *bvp = nullptr;
    if (GATED) {
        if (blockIdx.y == 0) { mg = 0; mv = 1; bgp = bg0; bvp = bv0; }
        else                 { mg = 2; mv = 3; bgp = bg1; bvp = bv1; }
    } else {
        mg = 4; bgp = bg0;
    }

    // --- async weight staging from pre-split scratch ---
    {
        const uint32_t wghA = smem_u32(Wgh), wglA = smem_u32(Wgl);
        const __nv_bfloat16* GH = g_wh + mg * 16384;
        const __nv_bfloat16* GL = g_wl + mg * 16384;
        const __nv_bfloat16* VH = GATED ? g_wh + mv * 16384 : nullptr;
        const __nv_bfloat16* VL = GATED ? g_wl + mv * 16384 : nullptr;
        const uint32_t wvhA = GATED ? smem_u32(Wvh) : 0;
        const uint32_t wvlA = GATED ? smem_u32(Wvl) : 0;
#pragma unroll
        for (int t = 0; t < 4; ++t) {
            int u = tid + t * NT;                 // 2048 chunks
            int r = u >> 4, c = u & 15;
            uint32_t doff = (uint32_t)(r * PITB + c * 16);
            int goff = r * 128 + c * 8;
            cp16(wghA + doff, GH + goff);
            cp16(wglA + doff, GL + goff);
            if (GATED) {
                cp16(wvhA + doff, VH + goff);
                cp16(wvlA + doff, VL + goff);
            }
        }
        CP_COMMIT();
    }

    if (tid < 128) {
        bgs[tid] = bgp[tid];
        if (GATED) { bvs[tid] = bvp[tid]; msm[tid] = mask[pix0 + tid]; }
    }

    // LayerNorm (overlapped with weight cp.async): batched row loads
    {
        float4 s4 = ((const float4*)ln_s)[lane];
        float4 b4 = ((const float4*)ln_b)[lane];
        float4 v[8];
#pragma unroll
        for (int t = 0; t < 8; ++t)
            v[t] = ((const float4*)(z + (size_t)(pix0 + t * 16 + wid) * CDIM))[lane];
#pragma unroll
        for (int t = 0; t < 8; ++t) {
            int r = t * 16 + wid;
            float s  = v[t].x + v[t].y + v[t].z + v[t].w;
            float ss = v[t].x*v[t].x + v[t].y*v[t].y + v[t].z*v[t].z + v[t].w*v[t].w;
#pragma unroll
            for (int o = 16; o > 0; o >>= 1) {
                s  += __shfl_xor_sync(0xffffffffu, s,  o);
                ss += __shfl_xor_sync(0xffffffffu, ss, o);
            }
            float mu   = s * 0.0078125f;
            float rstd = rsqrtf(ss * 0.0078125f - mu * mu + 1e-5f);
            float4 o4;
            o4.x = (v[t].x - mu) * rstd * s4.x + b4.x;
            o4.y = (v[t].y - mu) * rstd * s4.y + b4.y;
            o4.z = (v[t].z - mu) * rstd * s4.z + b4.z;
            o4.w = (v[t].w - mu) * rstd * s4.w + b4.w;
            uint2 hv, lv;
            split4(o4, hv, lv);
            *(uint2*)(&znh[r * PIT + lane * 4]) = hv;
            *(uint2*)(&znl[r * PIT + lane * 4]) = lv;
        }
    }
    CP_WAIT0();
    __syncthreads();

    const int wm = wid & 3, wn = wid >> 2;   // 4 (M) x 4 (N) warp grid
    const uint32_t zh = smem_u32(znh), zl = smem_u32(znl);
    const uint32_t wgh = smem_u32(Wgh), wgl = smem_u32(Wgl);
    const uint32_t wvh = GATED ? smem_u32(Wvh) : 0;
    const uint32_t wvl = GATED ? smem_u32(Wvl) : 0;

    float P[2][4][4], Q[2][4][4];
#pragma unroll
    for (int a = 0; a < 2; ++a)
#pragma unroll
        for (int b = 0; b < 4; ++b)
#pragma unroll
            for (int q = 0; q < 4; ++q) { P[a][b][q] = 0.f; if (GATED) Q[a][b][q] = 0.f; }

    if (GATED) {
        // A = W^T (trans): row k, col ch ; B = zn (non-trans): row p
        const int at_row = (lane & 7) + ((lane >> 4) << 3);
        const int at_col = ((lane >> 3) & 1) << 3;
        const int bp_row = wn * 32 + (lane & 7) + ((lane >> 4) << 3);
        const uint32_t bko = ((lane >> 3) & 1) * 16;

#pragma unroll
        for (int k16 = 0; k16 < 8; ++k16) {
            const int kb = k16 * 16;
            uint32_t bh[4][2], bl[4][2];
#pragma unroll
            for (int ng = 0; ng < 2; ++ng) {
                uint32_t r4[4];
                uint32_t boff = (uint32_t)((bp_row + ng * 16) * PITB) + kb * 2 + bko;
                ldsm4(zh + boff, r4);
                bh[ng*2][0] = r4[0]; bh[ng*2][1] = r4[1];
                bh[ng*2+1][0] = r4[2]; bh[ng*2+1][1] = r4[3];
                ldsm4(zl + boff, r4);
                bl[ng*2][0] = r4[0]; bl[ng*2][1] = r4[1];
                bl[ng*2+1][0] = r4[2]; bl[ng*2+1][1] = r4[3];
            }
            uint32_t aoff[2];
#pragma unroll
            for (int mt = 0; mt < 2; ++mt)
                aoff[mt] = (uint32_t)((kb + at_row) * PITB) +
                           (wm * 32 + mt * 16 + at_col) * 2;
            uint32_t a[2][4];
#pragma unroll
            for (int mt = 0; mt < 2; ++mt) ldsm4_t(wgh + aoff[mt], a[mt]);
#pragma unroll
            for (int mt = 0; mt < 2; ++mt)
#pragma unroll
                for (int nt = 0; nt < 4; ++nt) {
                    mma_bf16(P[mt][nt], a[mt], bh[nt]);
                    mma_bf16(P[mt][nt], a[mt], bl[nt]);
                }
#pragma unroll
            for (int mt = 0; mt < 2; ++mt) ldsm4_t(wgl + aoff[mt], a[mt]);
#pragma unroll
            for (int mt = 0; mt < 2; ++mt)
#pragma unroll
                for (int nt = 0; nt < 4; ++nt)
                    mma_bf16(P[mt][nt], a[mt], bh[nt]);
#pragma unroll
            for (int mt = 0; mt < 2; ++mt) ldsm4_t(wvh + aoff[mt], a[mt]);
#pragma unroll
            for (int mt = 0; mt < 2; ++mt)
#pragma unroll
                for (int nt = 0; nt < 4; ++nt) {
                    mma_bf16(Q[mt][nt], a[mt], bh[nt]);
                    mma_bf16(Q[mt][nt], a[mt], bl[nt]);
                }
#pragma unroll
            for (int mt = 0; mt < 2; ++mt) ldsm4_t(wvl + aoff[mt], a[mt]);
#pragma unroll
            for (int mt = 0; mt < 2; ++mt)
#pragma unroll
                for (int nt = 0; nt < 4; ++nt)
                    mma_bf16(Q[mt][nt], a[mt], bh[nt]);
        }

        // epilogue: mask * sig(P + bg) * (Q + bv) -> channel-major hi/lo
        __nv_bfloat16* oh = (blockIdx.y == 0) ? g_a_hi : g_b_hi;
        __nv_bfloat16* ol = (blockIdx.y == 0) ? g_a_lo : g_b_lo;
#pragma unroll
        for (int mt = 0; mt < 2; ++mt) {
            int ch = wm * 32 + mt * 16 + (lane >> 2);
            float bg0v = bgs[ch], bg1v = bgs[ch + 8];
            float bv0v = bvs[ch], bv1v = bvs[ch + 8];
            size_t r0 = (size_t)ch * NN + pix0;
            size_t r1 = (size_t)(ch + 8) * NN + pix0;
#pragma unroll
            for (int nt = 0; nt < 4; ++nt) {
                int p = wn * 32 + nt * 8 + (lane & 3) * 2;
                float m0 = msm[p], m1 = msm[p + 1];
                float v00 = m0 * sigmf(P[mt][nt][0] + bg0v) * (Q[mt][nt][0] + bv0v);
                float v01 = m1 * sigmf(P[mt][nt][1] + bg0v) * (Q[mt][nt][1] + bv0v);
                float v10 = m0 * sigmf(P[mt][nt][2] + bg1v) * (Q[mt][nt][2] + bv1v);
                float v11 = m1 * sigmf(P[mt][nt][3] + bg1v) * (Q[mt][nt][3] + bv1v);
                *(uint32_t*)(oh + r0 + p) = pk_bf16x2(v00, v01);
                *(uint32_t*)(ol + r0 + p) = pk_bf16x2(bf16_res(v00), bf16_res(v01));
                *(uint32_t*)(oh + r1 + p) = pk_bf16x2(v10, v11);
                *(uint32_t*)(ol + r1 + p) = pk_bf16x2(bf16_res(v10), bf16_res(v11));
            }
        }
    } else {
        // A = zn (non-trans): row p ; B = W^T (trans): row k, col ch
        const int a_row = wm * 32 + (lane & 15);
        const uint32_t ako = (lane >> 4) * 16;
        const int bt_row = (lane & 7) + (((lane >> 3) & 1) << 3);
        const int bt_col = (lane >> 4) << 3;

#pragma unroll
        for (int k16 = 0; k16 < 8; ++k16) {
            const int kb = k16 * 16;
            uint32_t bh[4][2], bl[4][2];
#pragma unroll
            for (int ng = 0; ng < 2; ++ng) {
                uint32_t r4[4];
                uint32_t boff = (uint32_t)((kb + bt_row) * PITB) +
                                (wn * 32 + ng * 16 + bt_col) * 2;
                ldsm4_t(wgh + boff, r4);
                bh[ng*2][0] = r4[0]; bh[ng*2][1] = r4[1];
                bh[ng*2+1][0] = r4[2]; bh[ng*2+1][1] = r4[3];
                ldsm4_t(wgl + boff, r4);
                bl[ng*2][0] = r4[0]; bl[ng*2][1] = r4[1];
                bl[ng*2+1][0] = r4[2]; bl[ng*2+1][1] = r4[3];
            }
            uint32_t ah[2][4], al[2][4];
#pragma unroll
            for (int mt = 0; mt < 2; ++mt) {
                uint32_t aoff = (uint32_t)((a_row + mt * 16) * PITB) + kb * 2 + ako;
                ldsm4(zh + aoff, ah[mt]);
                ldsm4(zl + aoff, al[mt]);
            }
#pragma unroll
            for (int mt = 0; mt < 2; ++mt)
#pragma unroll
                for (int nt = 0; nt < 4; ++nt) {
                    mma_bf16(P[mt][nt], ah[mt], bh[nt]);
                    mma_bf16(P[mt][nt], ah[mt], bl[nt]);
                    mma_bf16(P[mt][nt], al[mt], bh[nt]);
                }
        }

        // epilogue: sigmoid -> g_g[p][ch]
#pragma unroll
        for (int mt = 0; mt < 2; ++mt) {
            int p0 = pix0 + wm * 32 + mt * 16 + (lane >> 2);
#pragma unroll
            for (int nt = 0; nt < 4; ++nt) {
                int ch = wn * 32 + nt * 8 + (lane & 3) * 2;
                float b0 = bgs[ch], b1 = bgs[ch + 1];
                float2 v0 = make_float2(sigmf(P[mt][nt][0] + b0),
                                        sigmf(P[mt][nt][1] + b1));
                float2 v1 = make_float2(sigmf(P[mt][nt][2] + b0),
                                        sigmf(P[mt][nt][3] + b1));
                *(float2*)(g_g + (size_t)p0 * CDIM + ch) = v0;
                *(float2*)(g_g + (size_t)(p0 + 8) * CDIM + ch) = v1;
            }
        }
    }
}

// ---------------------------------------------------------------------------
// Kernel 2: per-channel X_c = A_c @ B_c^T via mma.sync bf16 hi/lo split.
// (unchanged from round 5)
// ---------------------------------------------------------------------------
#define K2S 65536u

__global__ void __launch_bounds__(NT, 1)
k2_mma()
{
    extern __shared__ char sm2[];
    const uint32_t smb = smem_u32(sm2);
    const int tid  = threadIdx.x;
    const int lane = tid & 31, wid = tid >> 5;
    const int wm = wid & 3, wn = wid >> 2;
    const int i0 = blockIdx.x * 128, j0 = blockIdx.y * 128;
    const size_t cbase = (size_t)blockIdx.z * NN;

    const __nv_bfloat16* Ah = g_a_hi + cbase + (size_t)i0 * NSEQ;
    const __nv_bfloat16* Al = g_a_lo + cbase + (size_t)i0 * NSEQ;
    const __nv_bfloat16* Bh = g_b_hi + cbase + (size_t)j0 * NSEQ;
    const __nv_bfloat16* Bl = g_b_lo + cbase + (size_t)j0 * NSEQ;

    float acc[2][4][4];
#pragma unroll
    for (int mt = 0; mt < 2; ++mt)
#pragma unroll
        for (int nt = 0; nt < 4; ++nt)
#pragma unroll
            for (int q = 0; q < 4; ++q) acc[mt][nt][q] = 0.f;

    const int arow = wm * 32 + (lane & 15);
    const int bnr  = wn * 32 + (lane & 7) + ((lane >> 4) << 3);
    const uint32_t a_koff = (uint32_t)((lane >> 4) << 4);
    const uint32_t b_koff = (uint32_t)(((lane >> 3) & 1) << 4);

#define K2_LOAD(kc, stg)                                                      \
    do {                                                                      \
        const int ke = (kc) * 64;                                             \
        _Pragma("unroll")                                                     \
        for (int t = 0; t < 2; ++t) {                                         \
            int v = tid + t * NT; int r = v >> 3, cu = v & 7;                 \
            uint32_t so = SWZ((uint32_t)(r * 128 + cu * 16));                 \
            const size_t go = (size_t)r * NSEQ + ke + cu * 8;                 \
            cp16((stg) + so,           Ah + go);                              \
            cp16((stg) + 16384u + so,  Al + go);                              \
            cp16((stg) + 32768u + so,  Bh + go);                              \
            cp16((stg) + 49152u + so,  Bl + go);                              \
        }                                                                     \
        asm volatile("cp.async.commit_group;" ::: "memory");                  \
    } while (0)

    K2_LOAD(0, smb);

    for (int kc = 0; kc < 8; ++kc) {
        const uint32_t stg = smb + (uint32_t)(kc & 1) * K2S;
        if (kc < 7) K2_LOAD(kc + 1, smb + (uint32_t)((kc + 1) & 1) * K2S);
        if (kc < 7) asm volatile("cp.async.wait_group 1;" ::: "memory");
        else        asm volatile("cp.async.wait_group 0;" ::: "memory");
        __syncthreads();

#pragma unroll
        for (int k16 = 0; k16 < 4; ++k16) {
            const uint32_t kbA = (uint32_t)(k16 * 32) + a_koff;
            const uint32_t kbB = (uint32_t)(k16 * 32) + b_koff;
            uint32_t bh[4][2], bl[4][2];
#pragma unroll
            for (int ng = 0; ng < 2; ++ng) {
                uint32_t r4[4];
                uint32_t off = SWZ((uint32_t)((bnr + ng * 16) * 128) + kbB);
                ldsm4(stg + 32768u + off, r4);
                bh[ng * 2 + 0][0] = r4[0]; bh[ng * 2 + 0][1] = r4[1];
                bh[ng * 2 + 1][0] = r4[2]; bh[ng * 2 + 1][1] = r4[3];
                ldsm4(stg + 49152u + off, r4);
                bl[ng * 2 + 0][0] = r4[0]; bl[ng * 2 + 0][1] = r4[1];
                bl[ng * 2 + 1][0] = r4[2]; bl[ng * 2 + 1][1] = r4[3];
            }
#pragma unroll
            for (int mt = 0; mt < 2; ++mt) {
                uint32_t ah[4], al[4];
                uint32_t off = SWZ((uint32_t)((arow + mt * 16) * 128) + kbA);
                ldsm4(stg + off, ah);
                ldsm4(stg + 16384u + off, al);
#pragma unroll
                for (int nt = 0; nt < 4; ++nt) {
                    mma_bf16(acc[mt][nt], ah, bh[nt]);
                    mma_bf16(acc[mt][nt], ah, bl[nt]);
                    mma_bf16(acc[mt][nt], al, bh[nt]);
                }
            }
        }
        __syncthreads();
    }

    float* Xg = g_x + cbase + (size_t)(i0 + wm * 32) * NSEQ + j0 + wn * 32;
    const int rr = lane >> 2, cc = (lane & 3) * 2;
#pragma unroll
    for (int mt = 0; mt < 2; ++mt)
#pragma unroll
        for (int nt = 0; nt < 4; ++nt) {
            float* p0 = Xg + (size_t)(mt * 16 + rr) * NSEQ + nt * 8 + cc;
            *(float2*)p0              = make_float2(acc[mt][nt][0], acc[mt][nt][1]);
            *(float2*)(p0 + 8 * NSEQ) = make_float2(acc[mt][nt][2], acc[mt][nt][3]);
        }
#undef K2_LOAD
}

// ---------------------------------------------------------------------------
// Kernel 3: LN over channels + @w_out + b_out (mma.sync split), * g -> out.
// g_x tile and pre-split w_out staged via cp.async.
// ---------------------------------------------------------------------------
__global__ void __launch_bounds__(NT, 1)
k3_mma(const float* __restrict__ ln_s, const float* __restrict__ ln_b,
       const float* __restrict__ b_out, float* __restrict__ out)
{
    extern __shared__ char smraw[];
    float* Xs = (float*)smraw;                          // [c][p] pitch 128
    __nv_bfloat16* Xnh = (__nv_bfloat16*)(Xs + 16384);  // [c][p] pitch 136
    __nv_bfloat16* Xnl = Xnh + 128 * PIT;
    __nv_bfloat16* Wh  = Xnl + 128 * PIT;               // [k][n] pitch 136
    __nv_bfloat16* Wl  = Wh + 128 * PIT;
    float* so   = (float*)(Wl + 128 * PIT);
    float* bo   = so + 128;
    float* bou  = bo + 128;
    float* redS = bou + 128;     // 512
    float* redQ = redS + 512;    // 512
    float* mus  = redQ + 512;    // 128
    float* rss  = mus + 128;     // 128

    const int tid = threadIdx.x, lane = tid & 31, wid = tid >> 5;
    const int pix0 = blockIdx.x * 128;

    // async stage: g_x tile (fp32) + pre-split w_out (bf16 hi/lo)
    {
        const uint32_t xsA = smem_u32(Xs);
        const uint32_t whA = smem_u32(Wh), wlA = smem_u32(Wl);
        const __nv_bfloat16* GH = g_wh + 5 * 16384;
        const __nv_bfloat16* GL = g_wl + 5 * 16384;
#pragma unroll
        for (int t = 0; t < 8; ++t) {
            int u = tid + t * NT;                // 4096 chunks of g_x
            int c = u >> 5, q = u & 31;
            cp16(xsA + (uint32_t)(c * 512 + q * 16),
                 g_x + (size_t)c * NN + pix0 + q * 4);
        }
#pragma unroll
        for (int t = 0; t < 4; ++t) {
            int u = tid + t * NT;                // 2048 chunks per matrix
            int r = u >> 4, c = u & 15;
            uint32_t doff = (uint32_t)(r * PITB + c * 16);
            int goff = r * 128 + c * 8;
            cp16(whA + doff, GH + goff);
            cp16(wlA + doff, GL + goff);
        }
        CP_COMMIT();
    }
    if (tid < 128) { so[tid] = ln_s[tid]; bo[tid] = ln_b[tid]; bou[tid] = b_out[tid]; }
    CP_WAIT0();
    __syncthreads();

    // LN stats over c (four threads per pixel, 32 channels each)
    const int p = tid & 127, quarter = tid >> 7;
    {
        float s = 0.f, ss = 0.f;
        for (int c = quarter * 32; c < quarter * 32 + 32; ++c) {
            float v = Xs[c * 128 + p];
            s += v; ss += v * v;
        }
        redS[tid] = s; redQ[tid] = ss;
    }
    __syncthreads();
    if (tid < 128) {
        float S  = redS[tid] + redS[tid + 128] + redS[tid + 256] + redS[tid + 384];
        float Qv = redQ[tid] + redQ[tid + 128] + redQ[tid + 256] + redQ[tid + 384];
        float mu = S * 0.0078125f;
        mus[tid] = mu;
        rss[tid] = rsqrtf(Qv * 0.0078125f - mu * mu + 1e-5f);
    }
    __syncthreads();

    // normalize + split -> Xnh/Xnl [c][p]
    for (int u = tid; u < 4096; u += NT) {
        int c = u >> 5, p4 = (u & 31) * 4;
        float4 v = *(float4*)(Xs + c * 128 + p4);
        float4 m4 = *(float4*)(mus + p4);
        float4 r4 = *(float4*)(rss + p4);
        float sc = so[c], bb = bo[c];
        float4 xn;
        xn.x = (v.x - m4.x) * r4.x * sc + bb;
        xn.y = (v.y - m4.y) * r4.y * sc + bb;
        xn.z = (v.z - m4.z) * r4.z * sc + bb;
        xn.w = (v.w - m4.w) * r4.w * sc + bb;
        uint2 hv, lv;
        split4(xn, hv, lv);
        *(uint2*)(&Xnh[c * PIT + p4]) = hv;
        *(uint2*)(&Xnl[c * PIT + p4]) = lv;
    }
    __syncthreads();

    const int wm = wid & 3, wn = wid >> 2;
    const uint32_t xh = smem_u32(Xnh), xl = smem_u32(Xnl);
    const uint32_t wh = smem_u32(Wh), wl = smem_u32(Wl);

    float acc[2][4][4];
#pragma unroll
    for (int a = 0; a < 2; ++a)
#pragma unroll
        for (int b = 0; b < 4; ++b)
#pragma unroll
            for (int q = 0; q < 4; ++q) acc[a][b][q] = 0.f;

    const int at_row = (lane & 7) + ((lane >> 4) << 3);
    const int at_col = ((lane >> 3) & 1) << 3;
    const int bt_row = (lane & 7) + (((lane >> 3) & 1) << 3);
    const int bt_col = (lane >> 4) << 3;

#pragma unroll
    for (int k16 = 0; k16 < 8; ++k16) {
        const int kb = k16 * 16;
        uint32_t bh[4][2], bl[4][2];
#pragma unroll
        for (int ng = 0; ng < 2; ++ng) {
            uint32_t r4[4];
            uint32_t boff = (uint32_t)((kb + bt_row) * PITB) +
                            (wn * 32 + ng * 16 + bt_col) * 2;
            ldsm4_t(wh + boff, r4);
            bh[ng*2][0] = r4[0]; bh[ng*2][1] = r4[1];
            bh[ng*2+1][0] = r4[2]; bh[ng*2+1][1] = r4[3];
            ldsm4_t(wl + boff, r4);
            bl[ng*2][0] = r4[0]; bl[ng*2][1] = r4[1];
            bl[ng*2+1][0] = r4[2]; bl[ng*2+1][1] = r4[3];
        }
        uint32_t ah[2][4], al[2][4];
#pragma unroll
        for (int mt = 0; mt < 2; ++mt) {
            uint32_t aoff = (uint32_t)((kb + at_row) * PITB) +
                            (wm * 32 + mt * 16 + at_col) * 2;
            ldsm4_t(xh + aoff, ah[mt]);
            ldsm4_t(xl + aoff, al[mt]);
        }
#pragma unroll
        for (int mt = 0; mt < 2; ++mt)
#pragma unroll
            for (int nt = 0; nt < 4; ++nt) {
                mma_bf16(acc[mt][nt], ah[mt], bh[nt]);
                mma_bf16(acc[mt][nt], ah[mt], bl[nt]);
                mma_bf16(acc[mt][nt], al[mt], bh[nt]);
            }
    }

    // epilogue: (acc + b_out) * g -> out[p][ch]
#pragma unroll
    for (int mt = 0; mt < 2; ++mt) {
        int p0 = pix0 + wm * 32 + mt * 16 + (lane >> 2);
#pragma unroll
        for (int nt = 0; nt < 4; ++nt) {
            int ch = wn * 32 + nt * 8 + (lane & 3) * 2;
            float b0 = bou[ch], b1 = bou[ch + 1];
            float2 g0 = *(const float2*)(g_g + (size_t)p0 * CDIM + ch);
            float2 g1 = *(const float2*)(g_g + (size_t)(p0 + 8) * CDIM + ch);
            float2 v0 = make_float2((acc[mt][nt][0] + b0) * g0.x,
                                    (acc[mt][nt][1] + b1) * g0.y);
            float2 v1 = make_float2((acc[mt][nt][2] + b0) * g1.x,
                                    (acc[mt][nt][3] + b1) * g1.y);
            *(float2*)(out + (size_t)p0 * CDIM + ch) = v0;
            *(float2*)(out + (size_t)(p0 + 8) * CDIM + ch) = v1;
        }
    }
}

// ---------------------------------------------------------------------------
extern "C" void kernel_launch(void* const* d_in, const int* in_sizes, int n_in,
                              void* d_out, int out_size)
{
    const float* z        = (const float*)d_in[0];
    const float* mask     = (const float*)d_in[1];
    const float* ln_in_s  = (const float*)d_in[2];
    const float* ln_in_b  = (const float*)d_in[3];
    const float* w_left   = (const float*)d_in[4];
    const float* b_left   = (const float*)d_in[5];
    const float* w_right  = (const float*)d_in[6];
    const float* b_right  = (const float*)d_in[7];
    const float* w_lgate  = (const float*)d_in[8];
    const float* b_lgate  = (const float*)d_in[9];
    const float* w_rgate  = (const float*)d_in[10];
    const float* b_rgate  = (const float*)d_in[11];
    const float* ln_out_s = (const float*)d_in[12];
    const float* ln_out_b = (const float*)d_in[13];
    const float* w_out    = (const float*)d_in[14];
    const float* b_out    = (const float*)d_in[15];
    const float* w_gate   = (const float*)d_in[16];
    const float* b_gate   = (const float*)d_in[17];
    float* out = (float*)d_out;

    const int smem1g = 6 * 128 * PIT * 2 + 3 * 128 * 4;      // 210432
    const int smem1p = 4 * 128 * PIT * 2 + 3 * 128 * 4;      // 140800
    const int smem2  = 2 * (int)K2S;                         // 131072
    const int smem3  = 16384 * 4 + 4 * 128 * PIT * 2 +
                       (3 * 128 + 2 * 512 + 2 * 128) * 4;    // ~212k

    cudaFuncSetAttribute(k1_mma<true>,  cudaFuncAttributeMaxDynamicSharedMemorySize, smem1g);
    cudaFuncSetAttribute(k1_mma<false>, cudaFuncAttributeMaxDynamicSharedMemorySize, smem1p);
    cudaFuncSetAttribute(k2_mma,        cudaFuncAttributeMaxDynamicSharedMemorySize, smem2);
    cudaFuncSetAttribute(k3_mma,        cudaFuncAttributeMaxDynamicSharedMemorySize, smem3);

    // 0) pre-split weights: lgate, left, rgate, right, gate, out
    k0_split<<<96, 256>>>(w_lgate, w_left, w_rgate, w_right, w_gate, w_out);

    // 1) a, b projections (gated)
    k1_mma<true><<<dim3(NN / 128, 2), NT, smem1g>>>(
        z, mask, ln_in_s, ln_in_b,
        b_lgate, b_left, b_rgate, b_right);

    // 2) output gate g
    k1_mma<false><<<dim3(NN / 128, 1), NT, smem1p>>>(
        z, mask, ln_in_s, ln_in_b,
        b_gate, nullptr, nullptr, nullptr);

    // 3) triangular einsum per channel
    k2_mma<<<dim3(NSEQ / 128, NSEQ / 128, CDIM), NT, smem2>>>();

    // 4) LN + out projection + gating
    k3_mma<<<dim3(NN / 128, 1), NT, smem3>>>(ln_out_s, ln_out_b, b_out, out);
}

// round 7
// speedup vs baseline: 3.0970x; 1.0499x over previous
#include <cuda_runtime.h>
#include <cuda_bf16.h>
#include <math.h>
#include <stddef.h>
#include <stdint.h>

// Triangle multiplicative update (outgoing), N=512, cz=ch=128, fp32 in/out.
// All GEMMs on tensor cores via mma.sync bf16 hi/lo split (3 passes, fp32 acc).
// Round 7: k1 merged into one 3-phase kernel (a, b, g from one LN pass);
//          k2 deepened to a 3-stage cp.async pipeline.

#define NSEQ 512
#define CDIM 128
#define NN   (NSEQ*NSEQ)          // 262144
#define PIT  136                  // bf16 smem pitch (elements)
#define PITB 272                  // bytes
#define NT   512                  // threads per CTA

__device__ __nv_bfloat16 g_a_hi[(size_t)CDIM * NN];
__device__ __nv_bfloat16 g_a_lo[(size_t)CDIM * NN];
__device__ __nv_bfloat16 g_b_hi[(size_t)CDIM * NN];
__device__ __nv_bfloat16 g_b_lo[(size_t)CDIM * NN];
__device__ float g_g[(size_t)NN * CDIM];   // g[pix][c]
__device__ float g_x[(size_t)CDIM * NN];   // xT[c][i][j]
// pre-split weights: 0=lgate 1=left 2=rgate 3=right 4=gate 5=out
__device__ __align__(16) __nv_bfloat16 g_wh[6 * 16384];
__device__ __align__(16) __nv_bfloat16 g_wl[6 * 16384];

__device__ __forceinline__ float sigmf(float x) {
    return 1.0f / (1.0f + __expf(-x));
}
__device__ __forceinline__ unsigned pk_bf16x2(float a, float b) {
    __nv_bfloat162 t = __floats2bfloat162_rn(a, b);
    return *reinterpret_cast<unsigned*>(&t);
}
__device__ __forceinline__ float bf16_res(float v) {   // v - bf16(v)
    return v - __bfloat162float(__float2bfloat16(v));
}
__device__ __forceinline__ uint32_t smem_u32(const void* p) {
    uint32_t a;
    asm("{ .reg .u64 t; cvta.to.shared.u64 t, %1; cvt.u32.u64 %0, t; }"
        : "=r"(a) : "l"(p));
    return a;
}
__device__ __forceinline__ void cp16(uint32_t dst, const void* src) {
    asm volatile("cp.async.cg.shared.global [%0], [%1], 16;"
                 :: "r"(dst), "l"(src) : "memory");
}
#define CP_COMMIT() asm volatile("cp.async.commit_group;" ::: "memory")
#define CP_WAIT0()  asm volatile("cp.async.wait_group 0;" ::: "memory")
#define SWZ(o) ((o) ^ (((o) >> 3) & 0x70))

__device__ __forceinline__ void ldsm4(uint32_t addr, uint32_t* r) {
    asm volatile("ldmatrix.sync.aligned.m8n8.x4.shared.b16 {%0,%1,%2,%3}, [%4];"
                 : "=r"(r[0]), "=r"(r[1]), "=r"(r[2]), "=r"(r[3]) : "r"(addr));
}
__device__ __forceinline__ void ldsm4_t(uint32_t addr, uint32_t* r) {
    asm volatile("ldmatrix.sync.aligned.m8n8.x4.trans.shared.b16 {%0,%1,%2,%3}, [%4];"
                 : "=r"(r[0]), "=r"(r[1]), "=r"(r[2]), "=r"(r[3]) : "r"(addr));
}
__device__ __forceinline__ void mma_bf16(float* c, const uint32_t* a,
                                         const uint32_t* b) {
    asm volatile(
        "mma.sync.aligned.m16n8k16.row.col.f32.bf16.bf16.f32 "
        "{%0,%1,%2,%3}, {%4,%5,%6,%7}, {%8,%9}, {%0,%1,%2,%3};"
        : "+f"(c[0]), "+f"(c[1]), "+f"(c[2]), "+f"(c[3])
        : "r"(a[0]), "r"(a[1]), "r"(a[2]), "r"(a[3]), "r"(b[0]), "r"(b[1]));
}

__device__ __forceinline__ void split4(float4 v, uint2& hv, uint2& lv) {
    hv.x = pk_bf16x2(v.x, v.y);
    hv.y = pk_bf16x2(v.z, v.w);
    lv.x = pk_bf16x2(bf16_res(v.x), bf16_res(v.y));
    lv.y = pk_bf16x2(bf16_res(v.z), bf16_res(v.w));
}

// ---------------------------------------------------------------------------
// Kernel 0: pre-split the 6 weight matrices to bf16 hi/lo scratch.
// ---------------------------------------------------------------------------
__global__ void __launch_bounds__(256)
k0_split(const float* __restrict__ w0, const float* __restrict__ w1,
         const float* __restrict__ w2, const float* __restrict__ w3,
         const float* __restrict__ w4, const float* __restrict__ w5)
{
    const float* ws[6] = {w0, w1, w2, w3, w4, w5};
    int idx = blockIdx.x * 256 + threadIdx.x;   // 24576 threads
    int m = idx >> 12;
    int e = (idx & 4095) * 4;
    float4 v = *(const float4*)(ws[m] + e);
    uint2 hv, lv;
    split4(v, hv, lv);
    *(uint2*)(g_wh + m * 16384 + e) = hv;
    *(uint2*)(g_wl + m * 16384 + e) = lv;
}

// ---------------------------------------------------------------------------
// Kernel 1: one LN pass, three projection phases (a, b, g) per 128-pixel tile.
// Weight restaging for the next phase is overlapped with the current epilogue.
// 16 warps: 4 (M) x 4 (N); warp tile 32x32.
// ---------------------------------------------------------------------------
__global__ void __launch_bounds__(NT, 1)
k1_all(const float* __restrict__ z, const float* __restrict__ mask,
       const float* __restrict__ ln_s, const float* __restrict__ ln_b,
       const float* __restrict__ b_lg, const float* __restrict__ b_l,
       const float* __restrict__ b_rg, const float* __restrict__ b_r,
       const float* __restrict__ b_g)
{
    extern __shared__ char smraw[];
    __nv_bfloat16* znh = (__nv_bfloat16*)smraw;           // [p][k] pitch 136
    __nv_bfloat16* znl = znh + 128 * PIT;
    __nv_bfloat16* W0h = znl + 128 * PIT;                 // gate weights
    __nv_bfloat16* W0l = W0h + 128 * PIT;
    __nv_bfloat16* W1h = W0l + 128 * PIT;                 // value weights
    __nv_bfloat16* W1l = W1h + 128 * PIT;
    float* bs = (float*)(W1l + 128 * PIT);
    // bs: [0)lg [128)l [256)rg [384)r [512)g [640)mask

    const int tid = threadIdx.x, lane = tid & 31, wid = tid >> 5;
    const int pix0 = blockIdx.x * 128;

    const uint32_t w0hA = smem_u32(W0h), w0lA = smem_u32(W0l);
    const uint32_t w1hA = smem_u32(W1h), w1lA = smem_u32(W1l);

    // stage one weight matrix pair (hi/lo) into dsth/dstl
#define STAGE_W(mi, dsth, dstl)                                               \
    do {                                                                      \
        const __nv_bfloat16* SH = g_wh + (mi) * 16384;                        \
        const __nv_bfloat16* SL = g_wl + (mi) * 16384;                        \
        _Pragma("unroll")                                                     \
        for (int t = 0; t < 4; ++t) {                                         \
            int u = tid + t * NT;                                             \
            int r = u >> 4, c = u & 15;                                       \
            uint32_t doff = (uint32_t)(r * PITB + c * 16);                    \
            int goff = r * 128 + c * 8;                                       \
            cp16((dsth) + doff, SH + goff);                                   \
            cp16((dstl) + doff, SL + goff);                                   \
        }                                                                     \
    } while (0)

    // --- stage phase-A weights (lgate -> W0, left -> W1) ---
    STAGE_W(0, w0hA, w0lA);
    STAGE_W(1, w1hA, w1lA);
    CP_COMMIT();

    // biases + mask
    {
        int which = tid >> 7, r = tid & 127;
        const float* bp[4] = {b_lg, b_l, b_rg, b_r};
        bs[tid] = bp[which][r];
        if (tid < 128) { bs[512 + tid] = b_g[tid]; bs[640 + tid] = mask[pix0 + tid]; }
    }

    // LayerNorm (overlaps with weight cp.async)
    {
        float4 s4 = ((const float4*)ln_s)[lane];
        float4 b4 = ((const float4*)ln_b)[lane];
        float4 v[8];
#pragma unroll
        for (int t = 0; t < 8; ++t)
            v[t] = ((const float4*)(z + (size_t)(pix0 + t * 16 + wid) * CDIM))[lane];
#pragma unroll
        for (int t = 0; t < 8; ++t) {
            int r = t * 16 + wid;
            float s  = v[t].x + v[t].y + v[t].z + v[t].w;
            float ss = v[t].x*v[t].x + v[t].y*v[t].y + v[t].z*v[t].z + v[t].w*v[t].w;
#pragma unroll
            for (int o = 16; o > 0; o >>= 1) {
                s  += __shfl_xor_sync(0xffffffffu, s,  o);
                ss += __shfl_xor_sync(0xffffffffu, ss, o);
            }
            float mu   = s * 0.0078125f;
            float rstd = rsqrtf(ss * 0.0078125f - mu * mu + 1e-5f);
            float4 o4;
            o4.x = (v[t].x - mu) * rstd * s4.x + b4.x;
            o4.y = (v[t].y - mu) * rstd * s4.y + b4.y;
            o4.z = (v[t].z - mu) * rstd * s4.z + b4.z;
            o4.w = (v[t].w - mu) * rstd * s4.w + b4.w;
            uint2 hv, lv;
            split4(o4, hv, lv);
            *(uint2*)(&znh[r * PIT + lane * 4]) = hv;
            *(uint2*)(&znl[r * PIT + lane * 4]) = lv;
        }
    }
    CP_WAIT0();
    __syncthreads();

    const int wm = wid & 3, wn = wid >> 2;   // 4 (M) x 4 (N) warp grid
    const uint32_t zh = smem_u32(znh), zl = smem_u32(znl);

    // ldmatrix lane mappings
    const int at_row = (lane & 7) + ((lane >> 4) << 3);      // trans A (W^T)
    const int at_col = ((lane >> 3) & 1) << 3;
    const int bp_row = wn * 32 + (lane & 7) + ((lane >> 4) << 3);  // non-trans B (zn)
    const uint32_t bko = ((lane >> 3) & 1) * 16;

    // ---- phases A (a) and B (b): gated, C[ch][p] orientation ----
#pragma unroll 1
    for (int ph = 0; ph < 2; ++ph) {
        float P[2][4][4], Q[2][4][4];
#pragma unroll
        for (int a = 0; a < 2; ++a)
#pragma unroll
            for (int b = 0; b < 4; ++b)
#pragma unroll
                for (int q = 0; q < 4; ++q) { P[a][b][q] = 0.f; Q[a][b][q] = 0.f; }

#pragma unroll
        for (int k16 = 0; k16 < 8; ++k16) {
            const int kb = k16 * 16;
            uint32_t bh[4][2], bl[4][2];
#pragma unroll
            for (int ng = 0; ng < 2; ++ng) {
                uint32_t r4[4];
                uint32_t boff = (uint32_t)((bp_row + ng * 16) * PITB) + kb * 2 + bko;
                ldsm4(zh + boff, r4);
                bh[ng*2][0] = r4[0]; bh[ng*2][1] = r4[1];
                bh[ng*2+1][0] = r4[2]; bh[ng*2+1][1] = r4[3];
                ldsm4(zl + boff, r4);
                bl[ng*2][0] = r4[0]; bl[ng*2][1] = r4[1];
                bl[ng*2+1][0] = r4[2]; bl[ng*2+1][1] = r4[3];
            }
            uint32_t aoff[2];
#pragma unroll
            for (int mt = 0; mt < 2; ++mt)
                aoff[mt] = (uint32_t)((kb + at_row) * PITB) +
                           (wm * 32 + mt * 16 + at_col) * 2;
            uint32_t a[2][4];
#pragma unroll
            for (int mt = 0; mt < 2; ++mt) ldsm4_t(w0hA + aoff[mt], a[mt]);
#pragma unroll
            for (int mt = 0; mt < 2; ++mt)
#pragma unroll
                for (int nt = 0; nt < 4; ++nt) {
                    mma_bf16(P[mt][nt], a[mt], bh[nt]);
                    mma_bf16(P[mt][nt], a[mt], bl[nt]);
                }
#pragma unroll
            for (int mt = 0; mt < 2; ++mt) ldsm4_t(w0lA + aoff[mt], a[mt]);
#pragma unroll
            for (int mt = 0; mt < 2; ++mt)
#pragma unroll
                for (int nt = 0; nt < 4; ++nt)
                    mma_bf16(P[mt][nt], a[mt], bh[nt]);
#pragma unroll
            for (int mt = 0; mt < 2; ++mt) ldsm4_t(w1hA + aoff[mt], a[mt]);
#pragma unroll
            for (int mt = 0; mt < 2; ++mt)
#pragma unroll
                for (int nt = 0; nt < 4; ++nt) {
                    mma_bf16(Q[mt][nt], a[mt], bh[nt]);
                    mma_bf16(Q[mt][nt], a[mt], bl[nt]);
                }
#pragma unroll
            for (int mt = 0; mt < 2; ++mt) ldsm4_t(w1lA + aoff[mt], a[mt]);
#pragma unroll
            for (int mt = 0; mt < 2; ++mt)
#pragma unroll
                for (int nt = 0; nt < 4; ++nt)
                    mma_bf16(Q[mt][nt], a[mt], bh[nt]);
        }

        __syncthreads();   // all warps done reading W0/W1
        // prefetch next phase's weights, overlapped with this epilogue
        if (ph == 0) { STAGE_W(2, w0hA, w0lA); STAGE_W(3, w1hA, w1lA); CP_COMMIT(); }
        else         { STAGE_W(4, w0hA, w0lA); CP_COMMIT(); }

        // epilogue: mask * sig(P + bg) * (Q + bv) -> channel-major hi/lo
        const float* bgp = bs + ph * 256;
        const float* bvp = bs + ph * 256 + 128;
        const float* msm = bs + 640;
        __nv_bfloat16* oh = (ph == 0) ? g_a_hi : g_b_hi;
        __nv_bfloat16* ol = (ph == 0) ? g_a_lo : g_b_lo;
#pragma unroll
        for (int mt = 0; mt < 2; ++mt) {
            int ch = wm * 32 + mt * 16 + (lane >> 2);
            float bg0v = bgp[ch], bg1v = bgp[ch + 8];
            float bv0v = bvp[ch], bv1v = bvp[ch + 8];
            size_t r0 = (size_t)ch * NN + pix0;
            size_t r1 = (size_t)(ch + 8) * NN + pix0;
#pragma unroll
            for (int nt = 0; nt < 4; ++nt) {
                int p = wn * 32 + nt * 8 + (lane & 3) * 2;
                float m0 = msm[p], m1 = msm[p + 1];
                float v00 = m0 * sigmf(P[mt][nt][0] + bg0v) * (Q[mt][nt][0] + bv0v);
                float v01 = m1 * sigmf(P[mt][nt][1] + bg0v) * (Q[mt][nt][1] + bv0v);
                float v10 = m0 * sigmf(P[mt][nt][2] + bg1v) * (Q[mt][nt][2] + bv1v);
                float v11 = m1 * sigmf(P[mt][nt][3] + bg1v) * (Q[mt][nt][3] + bv1v);
                *(uint32_t*)(oh + r0 + p) = pk_bf16x2(v00, v01);
                *(uint32_t*)(ol + r0 + p) = pk_bf16x2(bf16_res(v00), bf16_res(v01));
                *(uint32_t*)(oh + r1 + p) = pk_bf16x2(v10, v11);
                *(uint32_t*)(ol + r1 + p) = pk_bf16x2(bf16_res(v10), bf16_res(v11));
            }
        }
        CP_WAIT0();
        __syncthreads();
    }

    // ---- phase C: g = sig(zn @ Wg + bg), C[p][ch] orientation ----
    {
        const int a_row = wm * 32 + (lane & 15);
        const uint32_t ako = (lane >> 4) * 16;
        const int bt_row = (lane & 7) + (((lane >> 3) & 1) << 3);
        const int bt_col = (lane >> 4) << 3;

        float P[2][4][4];
#pragma unroll
        for (int a = 0; a < 2; ++a)
#pragma unroll
            for (int b = 0; b < 4; ++b)
#pragma unroll
                for (int q = 0; q < 4; ++q) P[a][b][q] = 0.f;

#pragma unroll
        for (int k16 = 0; k16 < 8; ++k16) {
            const int kb = k16 * 16;
            uint32_t bh[4][2], bl[4][2];
#pragma unroll
            for (int ng = 0; ng < 2; ++ng) {
                uint32_t r4[4];
                uint32_t boff = (uint32_t)((kb + bt_row) * PITB) +
                                (wn * 32 + ng * 16 + bt_col) * 2;
                ldsm4_t(w0hA + boff, r4);
                bh[ng*2][0] = r4[0]; bh[ng*2][1] = r4[1];
                bh[ng*2+1][0] = r4[2]; bh[ng*2+1][1] = r4[3];
                ldsm4_t(w0lA + boff, r4);
                bl[ng*2][0] = r4[0]; bl[ng*2][1] = r4[1];
                bl[ng*2+1][0] = r4[2]; bl[ng*2+1][1] = r4[3];
            }
            uint32_t ah[2][4], al[2][4];
#pragma unroll
            for (int mt = 0; mt < 2; ++mt) {
                uint32_t aoff = (uint32_t)((a_row + mt * 16) * PITB) + kb * 2 + ako;
                ldsm4(zh + aoff, ah[mt]);
                ldsm4(zl + aoff, al[mt]);
            }
#pragma unroll
            for (int mt = 0; mt < 2; ++mt)
#pragma unroll
                for (int nt = 0; nt < 4; ++nt) {
                    mma_bf16(P[mt][nt], ah[mt], bh[nt]);
                    mma_bf16(P[mt][nt], ah[mt], bl[nt]);
                    mma_bf16(P[mt][nt], al[mt], bh[nt]);
                }
        }

        const float* bgp = bs + 512;
#pragma unroll
        for (int mt = 0; mt < 2; ++mt) {
            int p0 = pix0 + wm * 32 + mt * 16 + (lane >> 2);
#pragma unroll
            for (int nt = 0; nt < 4; ++nt) {
                int ch = wn * 32 + nt * 8 + (lane & 3) * 2;
                float b0 = bgp[ch], b1 = bgp[ch + 1];
                float2 v0 = make_float2(sigmf(P[mt][nt][0] + b0),
                                        sigmf(P[mt][nt][1] + b1));
                float2 v1 = make_float2(sigmf(P[mt][nt][2] + b0),
                                        sigmf(P[mt][nt][3] + b1));
                *(float2*)(g_g + (size_t)p0 * CDIM + ch) = v0;
                *(float2*)(g_g + (size_t)(p0 + 8) * CDIM + ch) = v1;
            }
        }
    }
#undef STAGE_W
}

// ---------------------------------------------------------------------------
// Kernel 2: per-channel X_c = A_c @ B_c^T via mma.sync bf16 hi/lo split.
// 3-stage cp.async pipeline (prefetch depth 2).
// ---------------------------------------------------------------------------
#define K2S 65536u

__global__ void __launch_bounds__(NT, 1)
k2_mma()
{
    extern __shared__ char sm2[];
    const uint32_t smb = smem_u32(sm2);
    const int tid  = threadIdx.x;
    const int lane = tid & 31, wid = tid >> 5;
    const int wm = wid & 3, wn = wid >> 2;
    const int i0 = blockIdx.x * 128, j0 = blockIdx.y * 128;
    const size_t cbase = (size_t)blockIdx.z * NN;

    const __nv_bfloat16* Ah = g_a_hi + cbase + (size_t)i0 * NSEQ;
    const __nv_bfloat16* Al = g_a_lo + cbase + (size_t)i0 * NSEQ;
    const __nv_bfloat16* Bh = g_b_hi + cbase + (size_t)j0 * NSEQ;
    const __nv_bfloat16* Bl = g_b_lo + cbase + (size_t)j0 * NSEQ;

    float acc[2][4][4];
#pragma unroll
    for (int mt = 0; mt < 2; ++mt)
#pragma unroll
        for (int nt = 0; nt < 4; ++nt)
#pragma unroll
            for (int q = 0; q < 4; ++q) acc[mt][nt][q] = 0.f;

    const int arow = wm * 32 + (lane & 15);
    const int bnr  = wn * 32 + (lane & 7) + ((lane >> 4) << 3);
    const uint32_t a_koff = (uint32_t)((lane >> 4) << 4);
    const uint32_t b_koff = (uint32_t)(((lane >> 3) & 1) << 4);

#define K2_LOAD(kc, stg)                                                      \
    do {                                                                      \
        const int ke = (kc) * 64;                                             \
        _Pragma("unroll")                                                     \
        for (int t = 0; t < 2; ++t) {                                         \
            int v = tid + t * NT; int r = v >> 3, cu = v & 7;                 \
            uint32_t so = SWZ((uint32_t)(r * 128 + cu * 16));                 \
            const size_t go = (size_t)r * NSEQ + ke + cu * 8;                 \
            cp16((stg) + so,           Ah + go);                              \
            cp16((stg) + 16384u + so,  Al + go);                              \
            cp16((stg) + 32768u + so,  Bh + go);                              \
            cp16((stg) + 49152u + so,  Bl + go);                              \
        }                                                                     \
        asm volatile("cp.async.commit_group;" ::: "memory");                  \
    } while (0)

    K2_LOAD(0, smb);
    K2_LOAD(1, smb + K2S);

#pragma unroll 1
    for (int kc = 0; kc < 8; ++kc) {
        if (kc + 2 < 8) K2_LOAD(kc + 2, smb + (uint32_t)((kc + 2) % 3) * K2S);
        if (kc < 6)      asm volatile("cp.async.wait_group 2;" ::: "memory");
        else if (kc == 6) asm volatile("cp.async.wait_group 1;" ::: "memory");
        else              asm volatile("cp.async.wait_group 0;" ::: "memory");
        __syncthreads();
        const uint32_t stg = smb + (uint32_t)(kc % 3) * K2S;

#pragma unroll
        for (int k16 = 0; k16 < 4; ++k16) {
            const uint32_t kbA = (uint32_t)(k16 * 32) + a_koff;
            const uint32_t kbB = (uint32_t)(k16 * 32) + b_koff;
            uint32_t bh[4][2], bl[4][2];
#pragma unroll
            for (int ng = 0; ng < 2; ++ng) {
                uint32_t r4[4];
                uint32_t off = SWZ((uint32_t)((bnr + ng * 16) * 128) + kbB);
                ldsm4(stg + 32768u + off, r4);
                bh[ng * 2 + 0][0] = r4[0]; bh[ng * 2 + 0][1] = r4[1];
                bh[ng * 2 + 1][0] = r4[2]; bh[ng * 2 + 1][1] = r4[3];
                ldsm4(stg + 49152u + off, r4);
                bl[ng * 2 + 0][0] = r4[0]; bl[ng * 2 + 0][1] = r4[1];
                bl[ng * 2 + 1][0] = r4[2]; bl[ng * 2 + 1][1] = r4[3];
            }
#pragma unroll
            for (int mt = 0; mt < 2; ++mt) {
                uint32_t ah[4], al[4];
                uint32_t off = SWZ((uint32_t)((arow + mt * 16) * 128) + kbA);
                ldsm4(stg + off, ah);
                ldsm4(stg + 16384u + off, al);
#pragma unroll
                for (int nt = 0; nt < 4; ++nt) {
                    mma_bf16(acc[mt][nt], ah, bh[nt]);
                    mma_bf16(acc[mt][nt], ah, bl[nt]);
                    mma_bf16(acc[mt][nt], al, bh[nt]);
                }
            }
        }
        __syncthreads();
    }

    float* Xg = g_x + cbase + (size_t)(i0 + wm * 32) * NSEQ + j0 + wn * 32;
    const int rr = lane >> 2, cc = (lane & 3) * 2;
#pragma unroll
    for (int mt = 0; mt < 2; ++mt)
#pragma unroll
        for (int nt = 0; nt < 4; ++nt) {
            float* p0 = Xg + (size_t)(mt * 16 + rr) * NSEQ + nt * 8 + cc;
            *(float2*)p0              = make_float2(acc[mt][nt][0], acc[mt][nt][1]);
            *(float2*)(p0 + 8 * NSEQ) = make_float2(acc[mt][nt][2], acc[mt][nt][3]);
        }
#undef K2_LOAD
}

// ---------------------------------------------------------------------------
// Kernel 3: LN over channels + @w_out + b_out (mma.sync split), * g -> out.
// ---------------------------------------------------------------------------
__global__ void __launch_bounds__(NT, 1)
k3_mma(const float* __restrict__ ln_s, const float* __restrict__ ln_b,
       const float* __restrict__ b_out, float* __restrict__ out)
{
    extern __shared__ char smraw[];
    float* Xs = (float*)smraw;                          // [c][p] pitch 128
    __nv_bfloat16* Xnh = (__nv_bfloat16*)(Xs + 16384);  // [c][p] pitch 136
    __nv_bfloat16* Xnl = Xnh + 128 * PIT;
    __nv_bfloat16* Wh  = Xnl + 128 * PIT;               // [k][n] pitch 136
    __nv_bfloat16* Wl  = Wh + 128 * PIT;
    float* so   = (float*)(Wl + 128 * PIT);
    float* bo   = so + 128;
    float* bou  = bo + 128;
    float* redS = bou + 128;     // 512
    float* redQ = redS + 512;    // 512
    float* mus  = redQ + 512;    // 128
    float* rss  = mus + 128;     // 128

    const int tid = threadIdx.x, lane = tid & 31, wid = tid >> 5;
    const int pix0 = blockIdx.x * 128;

    // async stage: g_x tile (fp32) + pre-split w_out (bf16 hi/lo)
    {
        const uint32_t xsA = smem_u32(Xs);
        const uint32_t whA = smem_u32(Wh), wlA = smem_u32(Wl);
        const __nv_bfloat16* GH = g_wh + 5 * 16384;
        const __nv_bfloat16* GL = g_wl + 5 * 16384;
#pragma unroll
        for (int t = 0; t < 8; ++t) {
            int u = tid + t * NT;
            int c = u >> 5, q = u & 31;
            cp16(xsA + (uint32_t)(c * 512 + q * 16),
                 g_x + (size_t)c * NN + pix0 + q * 4);
        }
#pragma unroll
        for (int t = 0; t < 4; ++t) {
            int u = tid + t * NT;
            int r = u >> 4, c = u & 15;
            uint32_t doff = (uint32_t)(r * PITB + c * 16);
            int goff = r * 128 + c * 8;
            cp16(whA + doff, GH + goff);
            cp16(wlA + doff, GL + goff);
        }
        CP_COMMIT();
    }
    if (tid < 128) { so[tid] = ln_s[tid]; bo[tid] = ln_b[tid]; bou[tid] = b_out[tid]; }
    CP_WAIT0();
    __syncthreads();

    // LN stats over c (four threads per pixel, 32 channels each)
    const int p = tid & 127, quarter = tid >> 7;
    {
        float s = 0.f, ss = 0.f;
        for (int c = quarter * 32; c < quarter * 32 + 32; ++c) {
            float v = Xs[c * 128 + p];
            s += v; ss += v * v;
        }
        redS[tid] = s; redQ[tid] = ss;
    }
    __syncthreads();
    if (tid < 128) {
        float S  = redS[tid] + redS[tid + 128] + redS[tid + 256] + redS[tid + 384];
        float Qv = redQ[tid] + redQ[tid + 128] + redQ[tid + 256] + redQ[tid + 384];
        float mu = S * 0.0078125f;
        mus[tid] = mu;
        rss[tid] = rsqrtf(Qv * 0.0078125f - mu * mu + 1e-5f);
    }
    __syncthreads();

    // normalize + split -> Xnh/Xnl [c][p]
    for (int u = tid; u < 4096; u += NT) {
        int c = u >> 5, p4 = (u & 31) * 4;
        float4 v = *(float4*)(Xs + c * 128 + p4);
        float4 m4 = *(float4*)(mus + p4);
        float4 r4 = *(float4*)(rss + p4);
        float sc = so[c], bb = bo[c];
        float4 xn;
        xn.x = (v.x - m4.x) * r4.x * sc + bb;
        xn.y = (v.y - m4.y) * r4.y * sc + bb;
        xn.z = (v.z - m4.z) * r4.z * sc + bb;
        xn.w = (v.w - m4.w) * r4.w * sc + bb;
        uint2 hv, lv;
        split4(xn, hv, lv);
        *(uint2*)(&Xnh[c * PIT + p4]) = hv;
        *(uint2*)(&Xnl[c * PIT + p4]) = lv;
    }
    __syncthreads();

    const int wm = wid & 3, wn = wid >> 2;
    const uint32_t xh = smem_u32(Xnh), xl = smem_u32(Xnl);
    const uint32_t wh = smem_u32(Wh), wl = smem_u32(Wl);

    float acc[2][4][4];
#pragma unroll
    for (int a = 0; a < 2; ++a)
#pragma unroll
        for (int b = 0; b < 4; ++b)
#pragma unroll
            for (int q = 0; q < 4; ++q) acc[a][b][q] = 0.f;

    const int at_row = (lane & 7) + ((lane >> 4) << 3);
    const int at_col = ((lane >> 3) & 1) << 3;
    const int bt_row = (lane & 7) + (((lane >> 3) & 1) << 3);
    const int bt_col = (lane >> 4) << 3;

#pragma unroll
    for (int k16 = 0; k16 < 8; ++k16) {
        const int kb = k16 * 16;
        uint32_t bh[4][2], bl[4][2];
#pragma unroll
        for (int ng = 0; ng < 2; ++ng) {
            uint32_t r4[4];
            uint32_t boff = (uint32_t)((kb + bt_row) * PITB) +
                            (wn * 32 + ng * 16 + bt_col) * 2;
            ldsm4_t(wh + boff, r4);
            bh[ng*2][0] = r4[0]; bh[ng*2][1] = r4[1];
            bh[ng*2+1][0] = r4[2]; bh[ng*2+1][1] = r4[3];
            ldsm4_t(wl + boff, r4);
            bl[ng*2][0] = r4[0]; bl[ng*2][1] = r4[1];
            bl[ng*2+1][0] = r4[2]; bl[ng*2+1][1] = r4[3];
        }
        uint32_t ah[2][4], al[2][4];
#pragma unroll
        for (int mt = 0; mt < 2; ++mt) {
            uint32_t aoff = (uint32_t)((kb + at_row) * PITB) +
                            (wm * 32 + mt * 16 + at_col) * 2;
            ldsm4_t(xh + aoff, ah[mt]);
            ldsm4_t(xl + aoff, al[mt]);
        }
#pragma unroll
        for (int mt = 0; mt < 2; ++mt)
#pragma unroll
            for (int nt = 0; nt < 4; ++nt) {
                mma_bf16(acc[mt][nt], ah[mt], bh[nt]);
                mma_bf16(acc[mt][nt], ah[mt], bl[nt]);
                mma_bf16(acc[mt][nt], al[mt], bh[nt]);
            }
    }

    // epilogue: (acc + b_out) * g -> out[p][ch]
#pragma unroll
    for (int mt = 0; mt < 2; ++mt) {
        int p0 = pix0 + wm * 32 + mt * 16 + (lane >> 2);
#pragma unroll
        for (int nt = 0; nt < 4; ++nt) {
            int ch = wn * 32 + nt * 8 + (lane & 3) * 2;
            float b0 = bou[ch], b1 = bou[ch + 1];
            float2 g0 = *(const float2*)(g_g + (size_t)p0 * CDIM + ch);
            float2 g1 = *(const float2*)(g_g + (size_t)(p0 + 8) * CDIM + ch);
            float2 v0 = make_float2((acc[mt][nt][0] + b0) * g0.x,
                                    (acc[mt][nt][1] + b1) * g0.y);
            float2 v1 = make_float2((acc[mt][nt][2] + b0) * g1.x,
                                    (acc[mt][nt][3] + b1) * g1.y);
            *(float2*)(out + (size_t)p0 * CDIM + ch) = v0;
            *(float2*)(out + (size_t)(p0 + 8) * CDIM + ch) = v1;
        }
    }
}

// ---------------------------------------------------------------------------
extern "C" void kernel_launch(void* const* d_in, const int* in_sizes, int n_in,
                              void* d_out, int out_size)
{
    const float* z        = (const float*)d_in[0];
    const float* mask     = (const float*)d_in[1];
    const float* ln_in_s  = (const float*)d_in[2];
    const float* ln_in_b  = (const float*)d_in[3];
    const float* w_left   = (const float*)d_in[4];
    const float* b_left   = (const float*)d_in[5];
    const float* w_right  = (const float*)d_in[6];
    const float* b_right  = (const float*)d_in[7];
    const float* w_lgate  = (const float*)d_in[8];
    const float* b_lgate  = (const float*)d_in[9];
    const float* w_rgate  = (const float*)d_in[10];
    const float* b_rgate  = (const float*)d_in[11];
    const float* ln_out_s = (const float*)d_in[12];
    const float* ln_out_b = (const float*)d_in[13];
    const float* w_out    = (const float*)d_in[14];
    const float* b_out    = (const float*)d_in[15];
    const float* w_gate   = (const float*)d_in[16];
    const float* b_gate   = (const float*)d_in[17];
    float* out = (float*)d_out;

    const int smem1 = 6 * 128 * PIT * 2 + 6 * 128 * 4;       // 211968
    const int smem2 = 3 * (int)K2S;                          // 196608
    const int smem3 = 16384 * 4 + 4 * 128 * PIT * 2 +
                      (3 * 128 + 2 * 512 + 2 * 128) * 4;     // ~212k

    cudaFuncSetAttribute(k1_all, cudaFuncAttributeMaxDynamicSharedMemorySize, smem1);
    cudaFuncSetAttribute(k2_mma, cudaFuncAttributeMaxDynamicSharedMemorySize, smem2);
    cudaFuncSetAttribute(k3_mma, cudaFuncAttributeMaxDynamicSharedMemorySize, smem3);

    // 0) pre-split weights: lgate, left, rgate, right, gate, out
    k0_split<<<96, 256>>>(w_lgate, w_left, w_rgate, w_right, w_gate, w_out);

    // 1) a, b, g projections from a single LN pass
    k1_all<<<NN / 128, NT, smem1>>>(
        z, mask, ln_in_s, ln_in_b,
        b_lgate, b_left, b_rgate, b_right, b_gate);

    // 2) triangular einsum per channel
    k2_mma<<<dim3(NSEQ / 128, NSEQ / 128, CDIM), NT, smem2>>>();

    // 3) LN + out projection + gating
    k3_mma<<<NN / 128, NT, smem3>>>(ln_out_s, ln_out_b, b_out, out);
}